// round 10
// baseline (speedup 1.0000x reference)
#include <cuda_runtime.h>
#include <math_constants.h>
#include <stdint.h>

#define BATCH 8
#define CH 256
#define HH 128
#define WW 128
#define HWSZ 16384
#define NPTS 500
#define NPAD 512
#define NHID 16

typedef unsigned long long u64;

// ---------------- scratch ----------------
__device__ float g_score [BATCH * HWSZ];
__device__ float g_spart2[BATCH * HWSZ];
__device__ int   g_idx[BATCH * NPTS];
__device__ float g_vmt [BATCH * CH * NPAD];   // v_main transposed [b][c][n], zero-padded
__device__ float g_vat [BATCH * CH * NPAD];   // v_aux  transposed [b][c][n], zero-padded
__device__ float g_vaux[BATCH * NPAD * CH];   // v_aux row-major [b][n][c], rows >=500 zero

// ---------------- f32x2 helpers (fc1 path) ----------------
__device__ __forceinline__ u64 pk2(float x, float y) {
    u64 d; asm("mov.b64 %0, {%1, %2};" : "=l"(d) : "f"(x), "f"(y)); return d;
}
__device__ __forceinline__ void upk2(float& x, float& y, u64 d) {
    asm("mov.b64 {%0, %1}, %2;" : "=f"(x), "=f"(y) : "l"(d));
}
__device__ __forceinline__ u64 f2fma(u64 a, u64 b, u64 c) {
    u64 d; asm("fma.rn.f32x2 %0, %1, %2, %3;" : "=l"(d) : "l"(a), "l"(b), "l"(c)); return d;
}

// ---------------- tensor-core + cp.async helpers ----------------
__device__ __forceinline__ void mma8(float* d, const uint32_t* a, const uint32_t* b) {
    asm volatile(
        "mma.sync.aligned.m16n8k8.row.col.f32.tf32.tf32.f32 "
        "{%0,%1,%2,%3},{%4,%5,%6,%7},{%8,%9},{%0,%1,%2,%3};"
        : "+f"(d[0]), "+f"(d[1]), "+f"(d[2]), "+f"(d[3])
        : "r"(a[0]), "r"(a[1]), "r"(a[2]), "r"(a[3]), "r"(b[0]), "r"(b[1]));
}
__device__ __forceinline__ void cp16(const void* smem_dst, const float* gsrc) {
    uint32_t d;
    asm("{ .reg .u64 tt; cvta.to.shared.u64 tt, %1; cvt.u32.u64 %0, tt; }" : "=r"(d) : "l"(smem_dst));
    asm volatile("cp.async.cg.shared.global [%0], [%1], 16;" :: "r"(d), "l"(gsrc));
}
#define CP_COMMIT() asm volatile("cp.async.commit_group;")
#define CP_WAIT1()  asm volatile("cp.async.wait_group 1;")
#define CP_WAIT0()  asm volatile("cp.async.wait_group 0;")

// ================= kernel 1: fused copy + scorer, register-only partials =================
__global__ void __launch_bounds__(256) k1_copy_score(const float* __restrict__ xm,
                                                     const float* __restrict__ sw,
                                                     float* __restrict__ out) {
    __shared__ float s_w[128];
    int t = threadIdx.x, s = blockIdx.y;
    if (t < 128) s_w[t] = sw[s * 128 + t];
    __syncthreads();

    int p  = blockIdx.x * 256 + t;
    int b  = p >> 14;
    int hw = p & (HWSZ - 1);
    const float* src = xm + (size_t)(b * CH + s * 128) * HWSZ + hw;
    float*       dst = out + (size_t)(b * CH + s * 128) * HWSZ + hw;

    float a = 0.f;
    #pragma unroll 8
    for (int c = 0; c < 128; ++c) {
        float v = src[(size_t)c * HWSZ];
        dst[(size_t)c * HWSZ] = v;
        a += v * s_w[c];
    }
    (s == 0 ? g_score : g_spart2)[p] = a;
}

// ================= kernel 2: exact top-500 per batch via radix select =================
__global__ void k2_topk() {
    __shared__ unsigned hist[256];
    __shared__ unsigned sh_pref;
    __shared__ int sh_k;
    __shared__ int cntGT, eqcnt;
    __shared__ int eqbuf[1024];

    int b = blockIdx.x, t = threadIdx.x, bd = blockDim.x;
    const float* sc  = g_score  + b * HWSZ;
    const float* sc2 = g_spart2 + b * HWSZ;

    unsigned prefix = 0;
    int k = NPTS;
    for (int byte = 3; byte >= 0; --byte) {
        if (t < 256) hist[t] = 0;
        __syncthreads();
        int shamt = byte * 8;
        for (int i = t; i < HWSZ; i += bd) {
            unsigned u = __float_as_uint(sc[i] + sc2[i]);
            u = (u & 0x80000000u) ? ~u : (u | 0x80000000u);
            bool m = (byte == 3) || ((u >> (shamt + 8)) == prefix);
            if (m) atomicAdd(&hist[(u >> shamt) & 255u], 1u);
        }
        __syncthreads();
        if (t == 0) {
            int cum = 0, bin;
            for (bin = 255; bin >= 0; --bin) {
                int h = (int)hist[bin];
                if (cum + h >= k) break;
                cum += h;
            }
            if (bin < 0) bin = 0;
            sh_pref = (prefix << 8) | (unsigned)bin;
            sh_k = k - cum;
        }
        __syncthreads();
        prefix = sh_pref; k = sh_k;
        __syncthreads();
    }
    unsigned T = prefix;
    if (t == 0) { cntGT = 0; eqcnt = 0; }
    __syncthreads();
    for (int i = t; i < HWSZ; i += bd) {
        unsigned u = __float_as_uint(sc[i] + sc2[i]);
        u = (u & 0x80000000u) ? ~u : (u | 0x80000000u);
        if (u > T) {
            int p = atomicAdd(&cntGT, 1);
            if (p < NPTS) g_idx[b * NPTS + p] = i;
        } else if (u == T) {
            int e = atomicAdd(&eqcnt, 1);
            if (e < 1024) eqbuf[e] = i;
        }
    }
    __syncthreads();
    if (t == 0) {
        int need = k;
        int base = cntGT;
        int ec = eqcnt; if (ec > 1024) ec = 1024;
        if (ec > need) {
            for (int a = 1; a < ec; ++a) {
                int v = eqbuf[a]; int jj = a - 1;
                while (jj >= 0 && eqbuf[jj] > v) { eqbuf[jj + 1] = eqbuf[jj]; --jj; }
                eqbuf[jj + 1] = v;
            }
        }
        for (int e = 0; e < need && e < ec && base + e < NPTS; ++e)
            g_idx[b * NPTS + base + e] = eqbuf[e];
    }
}

// ================= kernel 3: stream plane -> pool from smem (round-5 structure) =================
__global__ void __launch_bounds__(256) k3_pool(const float* __restrict__ xm,
                                               const float* __restrict__ xa) {
    extern __shared__ float sp[];
    int* s_hw = (int*)(sp + HWSZ);
    int c = blockIdx.x, b = blockIdx.y, t = threadIdx.x;

    for (int i = t; i < NPTS; i += 256) s_hw[i] = g_idx[b * NPTS + i];

    #pragma unroll
    for (int s = 0; s < 2; ++s) {
        const float* src = (s == 0 ? xm : xa) + (size_t)(b * CH + c) * HWSZ;
        __syncthreads();
        for (int i = t; i < HWSZ / 4; i += 256)
            reinterpret_cast<float4*>(sp)[i] = reinterpret_cast<const float4*>(src)[i];
        __syncthreads();

        for (int p = t; p < NPTS; p += 256) {
            int hw = s_hw[p];
            int iy = hw >> 7, ix = hw & 127;
            float sum = 0.f, mx = -CUDART_INF_F;
            if (iy >= 3 && iy <= 124 && ix >= 3 && ix <= 124) {
                const float* base = sp + (iy - 3) * WW + (ix - 3);
                #pragma unroll
                for (int dy = 0; dy < 7; ++dy) {
                    #pragma unroll
                    for (int dx = 0; dx < 7; ++dx) {
                        float v = base[dy * WW + dx];
                        sum += v; mx = fmaxf(mx, v);
                    }
                }
            } else {
                #pragma unroll
                for (int dy = -3; dy <= 3; ++dy) {
                    int yy = iy + dy; float wy = 1.f;
                    if (yy < 0) { yy = 0; wy = 0.5f; } else if (yy > 127) { yy = 127; wy = 0.5f; }
                    #pragma unroll
                    for (int dx = -3; dx <= 3; ++dx) {
                        int xx = ix + dx; float wx = wy;
                        if (xx < 0) { xx = 0; wx *= 0.5f; } else if (xx > 127) { xx = 127; wx *= 0.5f; }
                        float v = sp[yy * WW + xx] * wx;
                        sum += v; mx = fmaxf(mx, v);
                    }
                }
            }
            float r = 0.5f * (sum * (1.f / 49.f) + mx);
            if (s == 0) {
                g_vmt[(b * CH + c) * NPAD + p] = r;
            } else {
                g_vat[(b * CH + c) * NPAD + p] = r;
                g_vaux[(b * NPAD + p) * CH + c] = r;
            }
        }
    }
}

// ================= kernel 4: tf32 mma attention, deep-sliced pipeline =================
// smem (floats):
//  Qt [256][40]                 @ 0      (10240)
//  S  [32][520] (S/P; later Vf[32][264]) @ 10240 (16640)
//  B  staging (2x16x520 K | 2x32x264 V/W | W1p+W2s) @ 26880 (16896)
//  Vh [32][264]                 @ 43776  (8448)
#define T_QT 0
#define T_S  10240
#define T_B  26880
#define T_VH 43776
#define T_TOT 52224

__global__ void __launch_bounds__(512, 1)
k4_attn(const float* __restrict__ fc1w, const float* __restrict__ fc1b,
        const float* __restrict__ fc2w, const float* __restrict__ fc2b,
        const float* __restrict__ pw,   const float* __restrict__ pb,
        float* __restrict__ out) {
    extern __shared__ float sm[];
    float* Qt = sm + T_QT;
    float* S  = sm + T_S;
    float* Bf = sm + T_B;
    float* Vh = sm + T_VH;

    const int t = threadIdx.x, lane = t & 31, w = t >> 5;
    const int gid = lane >> 2, tig = lane & 3;
    const int b = blockIdx.y;
    const int r0 = blockIdx.x * 32;
    const int nrows = min(32, NPTS - r0);

    // ---- stage Q [k][r] pitch 40 (raw fp32 used as tf32) ----
    for (int idx4 = t; idx4 < 2048; idx4 += 512) {
        int k = idx4 >> 3, i4 = (idx4 & 7) * 4;
        float4 v = *reinterpret_cast<const float4*>(&g_vmt[(b * CH + k) * NPAD + r0 + i4]);
        *reinterpret_cast<float4*>(&Qt[k * 40 + i4]) = v;
    }

    // ================= GEMM1: S[32][512] = Q[32][256] * K^T, scaled 1/16 =================
    // 16 k-slices of 16 rows, double-buffered in Bf (stride 8320 floats).
    {
        float dq[2][4][4] = {};
        const int ntb = w * 4;
        #pragma unroll
        for (int ii = 0; ii < 4; ++ii) {
            int op = t + ii * 512;
            int row = op >> 7, ch = op & 127;
            cp16(&Bf[row * 520 + ch * 4], &g_vat[(size_t)(b * CH + row) * NPAD + ch * 4]);
        }
        CP_COMMIT();
        for (int s = 0; s < 16; ++s) {
            if (s + 1 < 16) {
                int kbase = 16 * (s + 1);
                int bufo = ((s + 1) & 1) * 8320;
                #pragma unroll
                for (int ii = 0; ii < 4; ++ii) {
                    int op = t + ii * 512;
                    int row = op >> 7, ch = op & 127;
                    cp16(&Bf[bufo + row * 520 + ch * 4],
                         &g_vat[(size_t)(b * CH + kbase + row) * NPAD + ch * 4]);
                }
                CP_COMMIT();
                CP_WAIT1();
            } else {
                CP_WAIT0();
            }
            __syncthreads();
            const uint32_t* KS  = (const uint32_t*)&Bf[(s & 1) * 8320];
            const uint32_t* QtU = (const uint32_t*)Qt;
            #pragma unroll
            for (int kk = 0; kk < 2; ++kk) {
                int kg = 16 * s + 8 * kk;
                uint32_t A[2][4];
                int ka = (kg + tig) * 40;
                int kb = (kg + tig + 4) * 40;
                #pragma unroll
                for (int mt = 0; mt < 2; ++mt) {
                    int r = mt * 16 + gid;
                    A[mt][0] = QtU[ka + r];
                    A[mt][1] = QtU[ka + r + 8];
                    A[mt][2] = QtU[kb + r];
                    A[mt][3] = QtU[kb + r + 8];
                }
                #pragma unroll
                for (int j = 0; j < 4; ++j) {
                    int n0 = (ntb + j) * 8 + gid;
                    uint32_t B[2];
                    B[0] = KS[(8 * kk + tig) * 520 + n0];
                    B[1] = KS[(8 * kk + tig + 4) * 520 + n0];
                    mma8(dq[0][j], A[0], B);
                    mma8(dq[1][j], A[1], B);
                }
            }
            __syncthreads();
        }
        #pragma unroll
        for (int mt = 0; mt < 2; ++mt) {
            #pragma unroll
            for (int j = 0; j < 4; ++j) {
                int r = mt * 16 + gid;
                int n0 = (ntb + j) * 8 + 2 * tig;
                S[r * 520 + n0]           = dq[mt][j][0] * 0.0625f;
                S[r * 520 + n0 + 1]       = dq[mt][j][1] * 0.0625f;
                S[(r + 8) * 520 + n0]     = dq[mt][j][2] * 0.0625f;
                S[(r + 8) * 520 + n0 + 1] = dq[mt][j][3] * 0.0625f;
            }
        }
        __syncthreads();
    }

    // ================= softmax rows (normalized P left in S; m>=500 zeroed) =================
    #pragma unroll
    for (int i = 0; i < 2; ++i) {
        int r = 2 * w + i;
        float mxv = -CUDART_INF_F;
        for (int m = lane; m < NPTS; m += 32) mxv = fmaxf(mxv, S[r * 520 + m]);
        #pragma unroll
        for (int o = 16; o; o >>= 1) mxv = fmaxf(mxv, __shfl_xor_sync(0xffffffffu, mxv, o));
        float sum = 0.f;
        for (int m = lane; m < NPTS; m += 32) {
            float e = __expf(S[r * 520 + m] - mxv);
            S[r * 520 + m] = e;
            sum += e;
        }
        #pragma unroll
        for (int o = 16; o; o >>= 1) sum += __shfl_xor_sync(0xffffffffu, sum, o);
        float inv = 1.f / sum;
        for (int m = lane; m < 512; m += 32) {
            float v = (m < NPTS) ? S[r * 520 + m] * inv : 0.f;
            S[r * 520 + m] = v;
        }
    }
    __syncthreads();

    // ================= GEMM2: Vh[32][256] = P[32][512] * V[512][256] =================
    // 16 m-slices of 32 rows, double-buffered in Bf (stride 8448 floats).
    {
        float dv[2][2][4] = {};
        const int ntb2 = w * 2;
        #pragma unroll
        for (int ii = 0; ii < 4; ++ii) {
            int op = t + ii * 512;
            int row = op >> 6, ch = op & 63;
            cp16(&Bf[row * 264 + ch * 4], &g_vaux[(size_t)(b * NPAD + row) * CH + ch * 4]);
        }
        CP_COMMIT();
        for (int s = 0; s < 16; ++s) {
            if (s + 1 < 16) {
                int mb = 32 * (s + 1);
                int bufo = ((s + 1) & 1) * 8448;
                #pragma unroll
                for (int ii = 0; ii < 4; ++ii) {
                    int op = t + ii * 512;
                    int row = op >> 6, ch = op & 63;
                    cp16(&Bf[bufo + row * 264 + ch * 4],
                         &g_vaux[(size_t)(b * NPAD + mb + row) * CH + ch * 4]);
                }
                CP_COMMIT();
                CP_WAIT1();
            } else {
                CP_WAIT0();
            }
            __syncthreads();
            const uint32_t* VS = (const uint32_t*)&Bf[(s & 1) * 8448];
            const uint32_t* PU = (const uint32_t*)S;
            #pragma unroll
            for (int kk = 0; kk < 4; ++kk) {
                int k0 = 32 * s + 8 * kk;
                uint32_t A[2][4];
                #pragma unroll
                for (int mt = 0; mt < 2; ++mt) {
                    int r = mt * 16 + gid;
                    A[mt][0] = PU[r * 520 + k0 + tig];
                    A[mt][1] = PU[(r + 8) * 520 + k0 + tig];
                    A[mt][2] = PU[r * 520 + k0 + tig + 4];
                    A[mt][3] = PU[(r + 8) * 520 + k0 + tig + 4];
                }
                #pragma unroll
                for (int j = 0; j < 2; ++j) {
                    int n0 = (ntb2 + j) * 8 + gid;
                    uint32_t B[2];
                    B[0] = VS[(8 * kk + tig) * 264 + n0];
                    B[1] = VS[(8 * kk + tig + 4) * 264 + n0];
                    mma8(dv[0][j], A[0], B);
                    mma8(dv[1][j], A[1], B);
                }
            }
            __syncthreads();
        }
        #pragma unroll
        for (int mt = 0; mt < 2; ++mt) {
            #pragma unroll
            for (int j = 0; j < 2; ++j) {
                int r = mt * 16 + gid;
                int n0 = (ntb2 + j) * 8 + 2 * tig;
                Vh[r * 264 + n0]           = dv[mt][j][0];
                Vh[r * 264 + n0 + 1]       = dv[mt][j][1];
                Vh[(r + 8) * 264 + n0]     = dv[mt][j][2];
                Vh[(r + 8) * 264 + n0 + 1] = dv[mt][j][3];
            }
        }
        __syncthreads();
    }

    // ================= gated fusion MLP (fp32 exact) =================
    float* W1p = Bf;            // [256][32] interleaved (W1a,W1b)
    float* Vf  = S;             // [32][264] fused result (P dead)
    float* W2s = Bf + 8192;     // [16][256]
    for (int idx = t; idx < 4096; idx += 512) {
        int k = idx >> 4, j = idx & 15;
        float wa = fc1w[idx];
        float wb = fc1w[4096 + idx];
        float wc = fc1w[8192 + idx];
        W1p[k * 32 + 2 * j]     = wa + wc;
        W1p[k * 32 + 2 * j + 1] = wb - wc;
    }
    for (int idx = t; idx < 4096; idx += 512) W2s[idx] = fc2w[idx];
    __syncthreads();

    int jl = lane & 15, half = lane >> 4;
    float hreg[2];
    #pragma unroll
    for (int i = 0; i < 2; ++i) {
        int r = 2 * w + i;
        u64 hp = pk2(0.f, 0.f);
        int k0 = half * 128;
        #pragma unroll 4
        for (int k = k0; k < k0 + 128; ++k) {
            float vm = Qt[k * 40 + r];
            float vh = Vh[r * 264 + k];
            u64 wv = *reinterpret_cast<const u64*>(&W1p[k * 32 + 2 * jl]);
            hp = f2fma(pk2(vm, vh), wv, hp);
        }
        float hx, hy; upk2(hx, hy, hp);
        float h = hx + hy;
        h += __shfl_xor_sync(0xffffffffu, h, 16);
        h += fc1b[jl];
        hreg[i] = fmaxf(h, 0.f);
    }
    #pragma unroll
    for (int i = 0; i < 2; ++i) {
        int r = 2 * w + i;
        for (int cb = 0; cb < 256; cb += 32) {
            int c = cb + lane;
            float gg = fc2b[c];
            #pragma unroll
            for (int jj = 0; jj < 16; ++jj)
                gg += __shfl_sync(0xffffffffu, hreg[i], jj) * W2s[jj * 256 + c];
            gg = 1.f / (1.f + __expf(-gg));
            float vm = Qt[c * 40 + r];
            float vh = Vh[r * 264 + c];
            Vf[r * 264 + c] = vm + gg * (vm - vh);
        }
    }
    __syncthreads();

    // ================= GEMM3: v_inj = Vf[32][256] * proj_w[256][256]; scatter =================
    // 8 k-slices of 32 rows, double-buffered in Bf.
    {
        float dp[2][2][4] = {};
        const int ntb3 = w * 2;
        #pragma unroll
        for (int ii = 0; ii < 4; ++ii) {
            int op = t + ii * 512;
            int row = op >> 6, ch = op & 63;
            cp16(&Bf[row * 264 + ch * 4], &pw[(size_t)row * 256 + ch * 4]);
        }
        CP_COMMIT();
        for (int s = 0; s < 8; ++s) {
            if (s + 1 < 8) {
                int kbse = 32 * (s + 1);
                int bufo = ((s + 1) & 1) * 8448;
                #pragma unroll
                for (int ii = 0; ii < 4; ++ii) {
                    int op = t + ii * 512;
                    int row = op >> 6, ch = op & 63;
                    cp16(&Bf[bufo + row * 264 + ch * 4],
                         &pw[(size_t)(kbse + row) * 256 + ch * 4]);
                }
                CP_COMMIT();
                CP_WAIT1();
            } else {
                CP_WAIT0();
            }
            __syncthreads();
            const uint32_t* WS = (const uint32_t*)&Bf[(s & 1) * 8448];
            const uint32_t* FU = (const uint32_t*)Vf;
            #pragma unroll
            for (int kk = 0; kk < 4; ++kk) {
                int k0 = 32 * s + 8 * kk;
                uint32_t A[2][4];
                #pragma unroll
                for (int mt = 0; mt < 2; ++mt) {
                    int r = mt * 16 + gid;
                    A[mt][0] = FU[r * 264 + k0 + tig];
                    A[mt][1] = FU[(r + 8) * 264 + k0 + tig];
                    A[mt][2] = FU[r * 264 + k0 + tig + 4];
                    A[mt][3] = FU[(r + 8) * 264 + k0 + tig + 4];
                }
                #pragma unroll
                for (int j = 0; j < 2; ++j) {
                    int n0 = (ntb3 + j) * 8 + gid;
                    uint32_t B[2];
                    B[0] = WS[(8 * kk + tig) * 264 + n0];
                    B[1] = WS[(8 * kk + tig + 4) * 264 + n0];
                    mma8(dp[0][j], A[0], B);
                    mma8(dp[1][j], A[1], B);
                }
            }
            __syncthreads();
        }
        // scatter-add epilogue (indices unique per batch -> plain RMW)
        #pragma unroll
        for (int mt = 0; mt < 2; ++mt) {
            int r = mt * 16 + gid;
            int hw0 = (r < nrows)     ? g_idx[b * NPTS + r0 + r]     : -1;
            int hw1 = (r + 8 < nrows) ? g_idx[b * NPTS + r0 + r + 8] : -1;
            #pragma unroll
            for (int j = 0; j < 2; ++j) {
                int c = (ntb3 + j) * 8 + 2 * tig;
                float pb0 = pb[c], pb1 = pb[c + 1];
                if (hw0 >= 0) {
                    float* o0 = out + (size_t)(b * CH + c) * HWSZ + hw0;
                    o0[0]    += dp[mt][j][0] + pb0;
                    o0[HWSZ] += dp[mt][j][1] + pb1;
                }
                if (hw1 >= 0) {
                    float* o1 = out + (size_t)(b * CH + c) * HWSZ + hw1;
                    o1[0]    += dp[mt][j][2] + pb0;
                    o1[HWSZ] += dp[mt][j][3] + pb1;
                }
            }
        }
    }
}

// ================= launch =================
extern "C" void kernel_launch(void* const* d_in, const int* in_sizes, int n_in,
                              void* d_out, int out_size) {
    const float* xm   = (const float*)d_in[0];
    const float* xa   = (const float*)d_in[1];
    const float* sw   = (const float*)d_in[2];
    const float* fc1w = (const float*)d_in[4];
    const float* fc1b = (const float*)d_in[5];
    const float* fc2w = (const float*)d_in[6];
    const float* fc2b = (const float*)d_in[7];
    const float* pw   = (const float*)d_in[8];
    const float* pb   = (const float*)d_in[9];
    float* out = (float*)d_out;

    const int K3_SMEM = HWSZ * 4 + NPTS * 4;   // 67536 B
    const int K4_SMEM = T_TOT * 4;             // 208896 B
    cudaFuncSetAttribute(k3_pool, cudaFuncAttributeMaxDynamicSharedMemorySize, K3_SMEM);
    cudaFuncSetAttribute(k4_attn, cudaFuncAttributeMaxDynamicSharedMemorySize, K4_SMEM);

    k1_copy_score<<<dim3(512, 2), 256>>>(xm, sw, out);
    k2_topk<<<BATCH, 512>>>();
    k3_pool<<<dim3(CH, BATCH), 256, K3_SMEM>>>(xm, xa);
    k4_attn<<<dim3(16, BATCH), 512, K4_SMEM>>>(fc1w, fc1b, fc2w, fc2b, pw, pb, out);
}

// round 11
// speedup vs baseline: 1.0134x; 1.0134x over previous
#include <cuda_runtime.h>
#include <math_constants.h>
#include <stdint.h>

#define BATCH 8
#define CH 256
#define HH 128
#define WW 128
#define HWSZ 16384
#define NPTS 500
#define NPAD 512
#define NHID 16

typedef unsigned long long u64;

// ---------------- scratch ----------------
__device__ float g_score [BATCH * HWSZ];
__device__ float g_spart2[BATCH * HWSZ];
__device__ int   g_idx[BATCH * NPTS];
__device__ float g_vmt [BATCH * CH * NPAD];   // v_main transposed [b][c][n], zero-padded
__device__ float g_vat [BATCH * CH * NPAD];   // v_aux  transposed [b][c][n], zero-padded
__device__ float g_vaux[BATCH * NPAD * CH];   // v_aux row-major [b][n][c], rows >=500 zero

// ---------------- f32x2 helpers (fc1 path) ----------------
__device__ __forceinline__ u64 pk2(float x, float y) {
    u64 d; asm("mov.b64 %0, {%1, %2};" : "=l"(d) : "f"(x), "f"(y)); return d;
}
__device__ __forceinline__ void upk2(float& x, float& y, u64 d) {
    asm("mov.b64 {%0, %1}, %2;" : "=f"(x), "=f"(y) : "l"(d));
}
__device__ __forceinline__ u64 f2fma(u64 a, u64 b, u64 c) {
    u64 d; asm("fma.rn.f32x2 %0, %1, %2, %3;" : "=l"(d) : "l"(a), "l"(b), "l"(c)); return d;
}

// ---------------- tensor-core + cp.async helpers ----------------
__device__ __forceinline__ void mma8(float* d, const uint32_t* a, const uint32_t* b) {
    asm volatile(
        "mma.sync.aligned.m16n8k8.row.col.f32.tf32.tf32.f32 "
        "{%0,%1,%2,%3},{%4,%5,%6,%7},{%8,%9},{%0,%1,%2,%3};"
        : "+f"(d[0]), "+f"(d[1]), "+f"(d[2]), "+f"(d[3])
        : "r"(a[0]), "r"(a[1]), "r"(a[2]), "r"(a[3]), "r"(b[0]), "r"(b[1]));
}
__device__ __forceinline__ void cp16(const void* smem_dst, const float* gsrc) {
    uint32_t d;
    asm("{ .reg .u64 tt; cvta.to.shared.u64 tt, %1; cvt.u32.u64 %0, tt; }" : "=r"(d) : "l"(smem_dst));
    asm volatile("cp.async.cg.shared.global [%0], [%1], 16;" :: "r"(d), "l"(gsrc));
}
#define CP_COMMIT() asm volatile("cp.async.commit_group;")
#define CP_WAIT1()  asm volatile("cp.async.wait_group 1;")
#define CP_WAIT0()  asm volatile("cp.async.wait_group 0;")

// ================= kernel 1: fused copy + scorer, register-only partials =================
__global__ void __launch_bounds__(256) k1_copy_score(const float* __restrict__ xm,
                                                     const float* __restrict__ sw,
                                                     float* __restrict__ out) {
    __shared__ float s_w[128];
    int t = threadIdx.x, s = blockIdx.y;
    if (t < 128) s_w[t] = sw[s * 128 + t];
    __syncthreads();

    int p  = blockIdx.x * 256 + t;
    int b  = p >> 14;
    int hw = p & (HWSZ - 1);
    const float* src = xm + (size_t)(b * CH + s * 128) * HWSZ + hw;
    float*       dst = out + (size_t)(b * CH + s * 128) * HWSZ + hw;

    float a = 0.f;
    #pragma unroll 8
    for (int c = 0; c < 128; ++c) {
        float v = src[(size_t)c * HWSZ];
        dst[(size_t)c * HWSZ] = v;
        a += v * s_w[c];
    }
    (s == 0 ? g_score : g_spart2)[p] = a;
}

// ================= kernel 2: exact top-500 per batch via radix select =================
__global__ void k2_topk() {
    __shared__ unsigned hist[256];
    __shared__ unsigned sh_pref;
    __shared__ int sh_k;
    __shared__ int cntGT, eqcnt;
    __shared__ int eqbuf[1024];

    int b = blockIdx.x, t = threadIdx.x, bd = blockDim.x;
    const float* sc  = g_score  + b * HWSZ;
    const float* sc2 = g_spart2 + b * HWSZ;

    unsigned prefix = 0;
    int k = NPTS;
    for (int byte = 3; byte >= 0; --byte) {
        if (t < 256) hist[t] = 0;
        __syncthreads();
        int shamt = byte * 8;
        for (int i = t; i < HWSZ; i += bd) {
            unsigned u = __float_as_uint(sc[i] + sc2[i]);
            u = (u & 0x80000000u) ? ~u : (u | 0x80000000u);
            bool m = (byte == 3) || ((u >> (shamt + 8)) == prefix);
            if (m) atomicAdd(&hist[(u >> shamt) & 255u], 1u);
        }
        __syncthreads();
        if (t == 0) {
            int cum = 0, bin;
            for (bin = 255; bin >= 0; --bin) {
                int h = (int)hist[bin];
                if (cum + h >= k) break;
                cum += h;
            }
            if (bin < 0) bin = 0;
            sh_pref = (prefix << 8) | (unsigned)bin;
            sh_k = k - cum;
        }
        __syncthreads();
        prefix = sh_pref; k = sh_k;
        __syncthreads();
    }
    unsigned T = prefix;
    if (t == 0) { cntGT = 0; eqcnt = 0; }
    __syncthreads();
    for (int i = t; i < HWSZ; i += bd) {
        unsigned u = __float_as_uint(sc[i] + sc2[i]);
        u = (u & 0x80000000u) ? ~u : (u | 0x80000000u);
        if (u > T) {
            int p = atomicAdd(&cntGT, 1);
            if (p < NPTS) g_idx[b * NPTS + p] = i;
        } else if (u == T) {
            int e = atomicAdd(&eqcnt, 1);
            if (e < 1024) eqbuf[e] = i;
        }
    }
    __syncthreads();
    if (t == 0) {
        int need = k;
        int base = cntGT;
        int ec = eqcnt; if (ec > 1024) ec = 1024;
        if (ec > need) {
            for (int a = 1; a < ec; ++a) {
                int v = eqbuf[a]; int jj = a - 1;
                while (jj >= 0 && eqbuf[jj] > v) { eqbuf[jj + 1] = eqbuf[jj]; --jj; }
                eqbuf[jj + 1] = v;
            }
        }
        for (int e = 0; e < need && e < ec && base + e < NPTS; ++e)
            g_idx[b * NPTS + base + e] = eqbuf[e];
    }
}

// ================= kernel 3: stream plane -> pool from smem =================
__global__ void __launch_bounds__(256) k3_pool(const float* __restrict__ xm,
                                               const float* __restrict__ xa) {
    extern __shared__ float sp[];
    int* s_hw = (int*)(sp + HWSZ);
    int c = blockIdx.x, b = blockIdx.y, t = threadIdx.x;

    for (int i = t; i < NPTS; i += 256) s_hw[i] = g_idx[b * NPTS + i];

    #pragma unroll
    for (int s = 0; s < 2; ++s) {
        const float* src = (s == 0 ? xm : xa) + (size_t)(b * CH + c) * HWSZ;
        __syncthreads();
        for (int i = t; i < HWSZ / 4; i += 256)
            reinterpret_cast<float4*>(sp)[i] = reinterpret_cast<const float4*>(src)[i];
        __syncthreads();

        for (int p = t; p < NPTS; p += 256) {
            int hw = s_hw[p];
            int iy = hw >> 7, ix = hw & 127;
            float sum = 0.f, mx = -CUDART_INF_F;
            if (iy >= 3 && iy <= 124 && ix >= 3 && ix <= 124) {
                const float* base = sp + (iy - 3) * WW + (ix - 3);
                #pragma unroll
                for (int dy = 0; dy < 7; ++dy) {
                    #pragma unroll
                    for (int dx = 0; dx < 7; ++dx) {
                        float v = base[dy * WW + dx];
                        sum += v; mx = fmaxf(mx, v);
                    }
                }
            } else {
                #pragma unroll
                for (int dy = -3; dy <= 3; ++dy) {
                    int yy = iy + dy; float wy = 1.f;
                    if (yy < 0) { yy = 0; wy = 0.5f; } else if (yy > 127) { yy = 127; wy = 0.5f; }
                    #pragma unroll
                    for (int dx = -3; dx <= 3; ++dx) {
                        int xx = ix + dx; float wx = wy;
                        if (xx < 0) { xx = 0; wx *= 0.5f; } else if (xx > 127) { xx = 127; wx *= 0.5f; }
                        float v = sp[yy * WW + xx] * wx;
                        sum += v; mx = fmaxf(mx, v);
                    }
                }
            }
            float r = 0.5f * (sum * (1.f / 49.f) + mx);
            if (s == 0) {
                g_vmt[(b * CH + c) * NPAD + p] = r;
            } else {
                g_vat[(b * CH + c) * NPAD + p] = r;
                g_vaux[(b * NPAD + p) * CH + c] = r;
            }
        }
    }
}

// ================= kernel 4: tf32 mma attention, 16-row tiles, 2 CTAs/SM =================
// smem (floats):
//  Qt [256][24]                    @ 0      (6144)
//  S  [16][520] (S/P; later Vf[16][264]+W2s[4096]) @ 6144 (8320)
//  Bf staging (2x8x520 K | 2x16x264 V/W | W1p 8192) @ 14464 (8448)
//  Vh [16][264]                    @ 22912  (4224)
#define T_QT 0
#define T_S  6144
#define T_B  14464
#define T_VH 22912
#define T_TOT 27136

__global__ void __launch_bounds__(512, 2)
k4_attn(const float* __restrict__ fc1w, const float* __restrict__ fc1b,
        const float* __restrict__ fc2w, const float* __restrict__ fc2b,
        const float* __restrict__ pw,   const float* __restrict__ pb,
        float* __restrict__ out) {
    extern __shared__ float sm[];
    float* Qt = sm + T_QT;
    float* S  = sm + T_S;
    float* Bf = sm + T_B;
    float* Vh = sm + T_VH;

    const int t = threadIdx.x, lane = t & 31, w = t >> 5;
    const int gid = lane >> 2, tig = lane & 3;
    const int b = blockIdx.y;
    const int r0 = blockIdx.x * 16;
    const int nrows = min(16, NPTS - r0);

    // ---- stage Q [k][r] pitch 24 (raw fp32 as tf32); 16 cols per k-row ----
    for (int idx4 = t; idx4 < 1024; idx4 += 512) {
        int k = idx4 >> 2, i4 = (idx4 & 3) * 4;
        float4 v = *reinterpret_cast<const float4*>(&g_vmt[(b * CH + k) * NPAD + r0 + i4]);
        *reinterpret_cast<float4*>(&Qt[k * 24 + i4]) = v;
    }

    // ================= GEMM1: S[16][512] = Q[16][256] * K^T, scaled 1/16 =================
    // 32 k-slices of 8 rows, double-buffered (stride 4160 floats).
    {
        float dq[4][4] = {};
        const int ntb = w * 4;
        #pragma unroll
        for (int ii = 0; ii < 2; ++ii) {
            int op = t + ii * 512;
            int row = op >> 7, ch = op & 127;
            cp16(&Bf[row * 520 + ch * 4], &g_vat[(size_t)(b * CH + row) * NPAD + ch * 4]);
        }
        CP_COMMIT();
        for (int s = 0; s < 32; ++s) {
            if (s + 1 < 32) {
                int kbase = 8 * (s + 1);
                int bufo = ((s + 1) & 1) * 4160;
                #pragma unroll
                for (int ii = 0; ii < 2; ++ii) {
                    int op = t + ii * 512;
                    int row = op >> 7, ch = op & 127;
                    cp16(&Bf[bufo + row * 520 + ch * 4],
                         &g_vat[(size_t)(b * CH + kbase + row) * NPAD + ch * 4]);
                }
                CP_COMMIT();
                CP_WAIT1();
            } else {
                CP_WAIT0();
            }
            __syncthreads();
            const uint32_t* KS  = (const uint32_t*)&Bf[(s & 1) * 4160];
            const uint32_t* QtU = (const uint32_t*)Qt;
            int kg = 8 * s;
            uint32_t A[4];
            A[0] = QtU[(kg + tig) * 24 + gid];
            A[1] = QtU[(kg + tig) * 24 + gid + 8];
            A[2] = QtU[(kg + tig + 4) * 24 + gid];
            A[3] = QtU[(kg + tig + 4) * 24 + gid + 8];
            #pragma unroll
            for (int j = 0; j < 4; ++j) {
                int n0 = (ntb + j) * 8 + gid;
                uint32_t B[2];
                B[0] = KS[tig * 520 + n0];
                B[1] = KS[(tig + 4) * 520 + n0];
                mma8(dq[j], A, B);
            }
            __syncthreads();
        }
        #pragma unroll
        for (int j = 0; j < 4; ++j) {
            int n0 = (ntb + j) * 8 + 2 * tig;
            S[gid * 520 + n0]           = dq[j][0] * 0.0625f;
            S[gid * 520 + n0 + 1]       = dq[j][1] * 0.0625f;
            S[(gid + 8) * 520 + n0]     = dq[j][2] * 0.0625f;
            S[(gid + 8) * 520 + n0 + 1] = dq[j][3] * 0.0625f;
        }
        __syncthreads();
    }

    // ================= softmax (one row per warp; m>=500 zeroed) =================
    {
        int r = w;
        float mxv = -CUDART_INF_F;
        for (int m = lane; m < NPTS; m += 32) mxv = fmaxf(mxv, S[r * 520 + m]);
        #pragma unroll
        for (int o = 16; o; o >>= 1) mxv = fmaxf(mxv, __shfl_xor_sync(0xffffffffu, mxv, o));
        float sum = 0.f;
        for (int m = lane; m < NPTS; m += 32) {
            float e = __expf(S[r * 520 + m] - mxv);
            S[r * 520 + m] = e;
            sum += e;
        }
        #pragma unroll
        for (int o = 16; o; o >>= 1) sum += __shfl_xor_sync(0xffffffffu, sum, o);
        float inv = 1.f / sum;
        for (int m = lane; m < 512; m += 32) {
            float v = (m < NPTS) ? S[r * 520 + m] * inv : 0.f;
            S[r * 520 + m] = v;
        }
    }
    __syncthreads();

    // ================= GEMM2: Vh[16][256] = P[16][512] * V[512][256] =================
    // 32 m-slices of 16 rows, double-buffered (stride 4224 floats).
    {
        float dv[2][4] = {};
        const int ntb2 = w * 2;
        #pragma unroll
        for (int ii = 0; ii < 2; ++ii) {
            int op = t + ii * 512;
            int row = op >> 6, ch = op & 63;
            cp16(&Bf[row * 264 + ch * 4], &g_vaux[(size_t)(b * NPAD + row) * CH + ch * 4]);
        }
        CP_COMMIT();
        for (int s = 0; s < 32; ++s) {
            if (s + 1 < 32) {
                int mb = 16 * (s + 1);
                int bufo = ((s + 1) & 1) * 4224;
                #pragma unroll
                for (int ii = 0; ii < 2; ++ii) {
                    int op = t + ii * 512;
                    int row = op >> 6, ch = op & 63;
                    cp16(&Bf[bufo + row * 264 + ch * 4],
                         &g_vaux[(size_t)(b * NPAD + mb + row) * CH + ch * 4]);
                }
                CP_COMMIT();
                CP_WAIT1();
            } else {
                CP_WAIT0();
            }
            __syncthreads();
            const uint32_t* VS = (const uint32_t*)&Bf[(s & 1) * 4224];
            const uint32_t* PU = (const uint32_t*)S;
            #pragma unroll
            for (int kk = 0; kk < 2; ++kk) {
                int k0 = 16 * s + 8 * kk;
                uint32_t A[4];
                A[0] = PU[gid * 520 + k0 + tig];
                A[1] = PU[(gid + 8) * 520 + k0 + tig];
                A[2] = PU[gid * 520 + k0 + tig + 4];
                A[3] = PU[(gid + 8) * 520 + k0 + tig + 4];
                #pragma unroll
                for (int j = 0; j < 2; ++j) {
                    int n0 = (ntb2 + j) * 8 + gid;
                    uint32_t B[2];
                    B[0] = VS[(8 * kk + tig) * 264 + n0];
                    B[1] = VS[(8 * kk + tig + 4) * 264 + n0];
                    mma8(dv[j], A, B);
                }
            }
            __syncthreads();
        }
        #pragma unroll
        for (int j = 0; j < 2; ++j) {
            int n0 = (ntb2 + j) * 8 + 2 * tig;
            Vh[gid * 264 + n0]           = dv[j][0];
            Vh[gid * 264 + n0 + 1]       = dv[j][1];
            Vh[(gid + 8) * 264 + n0]     = dv[j][2];
            Vh[(gid + 8) * 264 + n0 + 1] = dv[j][3];
        }
        __syncthreads();
    }

    // ================= gated fusion MLP (fp32 exact) =================
    float* W1p = Bf;            // [256][32] interleaved (W1a,W1b)
    float* Vf  = S;             // [16][264] fused result (P dead)
    float* W2s = S + 4224;      // [16][256]
    for (int idx = t; idx < 4096; idx += 512) {
        int k = idx >> 4, j = idx & 15;
        float wa = fc1w[idx];
        float wb = fc1w[4096 + idx];
        float wc = fc1w[8192 + idx];
        W1p[k * 32 + 2 * j]     = wa + wc;
        W1p[k * 32 + 2 * j + 1] = wb - wc;
    }
    __syncthreads();   // W1p ready; W2s region written below overlaps old P (dead after GEMM2)
    for (int idx = t; idx < 4096; idx += 512) W2s[idx] = fc2w[idx];
    __syncthreads();

    int jl = lane & 15, half = lane >> 4;
    float hreg;
    {
        int r = w;
        u64 hp = pk2(0.f, 0.f);
        int k0 = half * 128;
        #pragma unroll 4
        for (int k = k0; k < k0 + 128; ++k) {
            float vm = Qt[k * 24 + r];
            float vh = Vh[r * 264 + k];
            u64 wv = *reinterpret_cast<const u64*>(&W1p[k * 32 + 2 * jl]);
            hp = f2fma(pk2(vm, vh), wv, hp);
        }
        float hx, hy; upk2(hx, hy, hp);
        float h = hx + hy;
        h += __shfl_xor_sync(0xffffffffu, h, 16);
        h += fc1b[jl];
        hreg = fmaxf(h, 0.f);
    }
    {
        int r = w;
        for (int cb = 0; cb < 256; cb += 32) {
            int c = cb + lane;
            float gg = fc2b[c];
            #pragma unroll
            for (int jj = 0; jj < 16; ++jj)
                gg += __shfl_sync(0xffffffffu, hreg, jj) * W2s[jj * 256 + c];
            gg = 1.f / (1.f + __expf(-gg));
            float vm = Qt[c * 24 + r];
            float vh = Vh[r * 264 + c];
            Vf[r * 264 + c] = vm + gg * (vm - vh);
        }
    }
    __syncthreads();

    // ================= GEMM3: v_inj = Vf[16][256] * proj_w[256][256]; scatter =================
    // 16 k-slices of 16 rows, double-buffered in Bf (W1p dead).
    {
        float dp[2][4] = {};
        const int ntb3 = w * 2;
        #pragma unroll
        for (int ii = 0; ii < 2; ++ii) {
            int op = t + ii * 512;
            int row = op >> 6, ch = op & 63;
            cp16(&Bf[row * 264 + ch * 4], &pw[(size_t)row * 256 + ch * 4]);
        }
        CP_COMMIT();
        for (int s = 0; s < 16; ++s) {
            if (s + 1 < 16) {
                int kbse = 16 * (s + 1);
                int bufo = ((s + 1) & 1) * 4224;
                #pragma unroll
                for (int ii = 0; ii < 2; ++ii) {
                    int op = t + ii * 512;
                    int row = op >> 6, ch = op & 63;
                    cp16(&Bf[bufo + row * 264 + ch * 4],
                         &pw[(size_t)(kbse + row) * 256 + ch * 4]);
                }
                CP_COMMIT();
                CP_WAIT1();
            } else {
                CP_WAIT0();
            }
            __syncthreads();
            const uint32_t* WS = (const uint32_t*)&Bf[(s & 1) * 4224];
            const uint32_t* FU = (const uint32_t*)Vf;
            #pragma unroll
            for (int kk = 0; kk < 2; ++kk) {
                int k0 = 16 * s + 8 * kk;
                uint32_t A[4];
                A[0] = FU[gid * 264 + k0 + tig];
                A[1] = FU[(gid + 8) * 264 + k0 + tig];
                A[2] = FU[gid * 264 + k0 + tig + 4];
                A[3] = FU[(gid + 8) * 264 + k0 + tig + 4];
                #pragma unroll
                for (int j = 0; j < 2; ++j) {
                    int n0 = (ntb3 + j) * 8 + gid;
                    uint32_t B[2];
                    B[0] = WS[(8 * kk + tig) * 264 + n0];
                    B[1] = WS[(8 * kk + tig + 4) * 264 + n0];
                    mma8(dp[j], A, B);
                }
            }
            __syncthreads();
        }
        // scatter-add epilogue (indices unique per batch -> plain RMW)
        int hw0 = (gid < nrows)     ? g_idx[b * NPTS + r0 + gid]     : -1;
        int hw1 = (gid + 8 < nrows) ? g_idx[b * NPTS + r0 + gid + 8] : -1;
        #pragma unroll
        for (int j = 0; j < 2; ++j) {
            int c = (ntb3 + j) * 8 + 2 * tig;
            float pb0 = pb[c], pb1 = pb[c + 1];
            if (hw0 >= 0) {
                float* o0 = out + (size_t)(b * CH + c) * HWSZ + hw0;
                o0[0]    += dp[j][0] + pb0;
                o0[HWSZ] += dp[j][1] + pb1;
            }
            if (hw1 >= 0) {
                float* o1 = out + (size_t)(b * CH + c) * HWSZ + hw1;
                o1[0]    += dp[j][2] + pb0;
                o1[HWSZ] += dp[j][3] + pb1;
            }
        }
    }
}

// ================= launch =================
extern "C" void kernel_launch(void* const* d_in, const int* in_sizes, int n_in,
                              void* d_out, int out_size) {
    const float* xm   = (const float*)d_in[0];
    const float* xa   = (const float*)d_in[1];
    const float* sw   = (const float*)d_in[2];
    const float* fc1w = (const float*)d_in[4];
    const float* fc1b = (const float*)d_in[5];
    const float* fc2w = (const float*)d_in[6];
    const float* fc2b = (const float*)d_in[7];
    const float* pw   = (const float*)d_in[8];
    const float* pb   = (const float*)d_in[9];
    float* out = (float*)d_out;

    const int K3_SMEM = HWSZ * 4 + NPTS * 4;   // 67536 B
    const int K4_SMEM = T_TOT * 4;             // 108544 B
    cudaFuncSetAttribute(k3_pool, cudaFuncAttributeMaxDynamicSharedMemorySize, K3_SMEM);
    cudaFuncSetAttribute(k4_attn, cudaFuncAttributeMaxDynamicSharedMemorySize, K4_SMEM);

    k1_copy_score<<<dim3(512, 2), 256>>>(xm, sw, out);
    k2_topk<<<BATCH, 512>>>();
    k3_pool<<<dim3(CH, BATCH), 256, K3_SMEM>>>(xm, xa);
    k4_attn<<<dim3(32, BATCH), 512, K4_SMEM>>>(fc1w, fc1b, fc2w, fc2b, pw, pb, out);
}

// round 12
// speedup vs baseline: 1.0227x; 1.0092x over previous
#include <cuda_runtime.h>
#include <math_constants.h>
#include <stdint.h>

#define BATCH 8
#define CH 256
#define HH 128
#define WW 128
#define HWSZ 16384
#define NPTS 500
#define NPAD 512
#define NHID 16

typedef unsigned long long u64;

// ---------------- scratch ----------------
__device__ float g_score [BATCH * HWSZ];
__device__ float g_spart2[BATCH * HWSZ];
__device__ int   g_idx[BATCH * NPTS];
__device__ float g_vmt [BATCH * CH * NPAD];   // v_main transposed [b][c][n], zero-padded
__device__ float g_vat [BATCH * CH * NPAD];   // v_aux  transposed [b][c][n], zero-padded
__device__ float g_vaux[BATCH * NPAD * CH];   // v_aux row-major [b][n][c], rows >=500 zero

// ---------------- f32x2 helpers (fc1 path) ----------------
__device__ __forceinline__ u64 pk2(float x, float y) {
    u64 d; asm("mov.b64 %0, {%1, %2};" : "=l"(d) : "f"(x), "f"(y)); return d;
}
__device__ __forceinline__ void upk2(float& x, float& y, u64 d) {
    asm("mov.b64 {%0, %1}, %2;" : "=f"(x), "=f"(y) : "l"(d));
}
__device__ __forceinline__ u64 f2fma(u64 a, u64 b, u64 c) {
    u64 d; asm("fma.rn.f32x2 %0, %1, %2, %3;" : "=l"(d) : "l"(a), "l"(b), "l"(c)); return d;
}

// ---------------- tensor-core + cp.async helpers ----------------
__device__ __forceinline__ void mma8(float* d, const uint32_t* a, const uint32_t* b) {
    asm volatile(
        "mma.sync.aligned.m16n8k8.row.col.f32.tf32.tf32.f32 "
        "{%0,%1,%2,%3},{%4,%5,%6,%7},{%8,%9},{%0,%1,%2,%3};"
        : "+f"(d[0]), "+f"(d[1]), "+f"(d[2]), "+f"(d[3])
        : "r"(a[0]), "r"(a[1]), "r"(a[2]), "r"(a[3]), "r"(b[0]), "r"(b[1]));
}
__device__ __forceinline__ void cp16(const void* smem_dst, const float* gsrc) {
    uint32_t d;
    asm("{ .reg .u64 tt; cvta.to.shared.u64 tt, %1; cvt.u32.u64 %0, tt; }" : "=r"(d) : "l"(smem_dst));
    asm volatile("cp.async.cg.shared.global [%0], [%1], 16;" :: "r"(d), "l"(gsrc));
}
#define CP_COMMIT() asm volatile("cp.async.commit_group;")
#define CP_WAIT1()  asm volatile("cp.async.wait_group 1;")
#define CP_WAIT0()  asm volatile("cp.async.wait_group 0;")

// ================= kernel 1: fused copy + scorer, register-only partials =================
__global__ void __launch_bounds__(256) k1_copy_score(const float* __restrict__ xm,
                                                     const float* __restrict__ sw,
                                                     float* __restrict__ out) {
    __shared__ float s_w[128];
    int t = threadIdx.x, s = blockIdx.y;
    if (t < 128) s_w[t] = sw[s * 128 + t];
    __syncthreads();

    int p  = blockIdx.x * 256 + t;
    int b  = p >> 14;
    int hw = p & (HWSZ - 1);
    const float* src = xm + (size_t)(b * CH + s * 128) * HWSZ + hw;
    float*       dst = out + (size_t)(b * CH + s * 128) * HWSZ + hw;

    float a = 0.f;
    #pragma unroll 8
    for (int c = 0; c < 128; ++c) {
        float v = src[(size_t)c * HWSZ];
        dst[(size_t)c * HWSZ] = v;
        a += v * s_w[c];
    }
    (s == 0 ? g_score : g_spart2)[p] = a;
}

// ================= kernel 2: exact top-500 per batch via radix select =================
__global__ void k2_topk() {
    __shared__ unsigned hist[256];
    __shared__ unsigned sh_pref;
    __shared__ int sh_k;
    __shared__ int cntGT, eqcnt;
    __shared__ int eqbuf[1024];

    int b = blockIdx.x, t = threadIdx.x, bd = blockDim.x;
    const float* sc  = g_score  + b * HWSZ;
    const float* sc2 = g_spart2 + b * HWSZ;

    unsigned prefix = 0;
    int k = NPTS;
    for (int byte = 3; byte >= 0; --byte) {
        if (t < 256) hist[t] = 0;
        __syncthreads();
        int shamt = byte * 8;
        for (int i = t; i < HWSZ; i += bd) {
            unsigned u = __float_as_uint(sc[i] + sc2[i]);
            u = (u & 0x80000000u) ? ~u : (u | 0x80000000u);
            bool m = (byte == 3) || ((u >> (shamt + 8)) == prefix);
            if (m) atomicAdd(&hist[(u >> shamt) & 255u], 1u);
        }
        __syncthreads();
        if (t == 0) {
            int cum = 0, bin;
            for (bin = 255; bin >= 0; --bin) {
                int h = (int)hist[bin];
                if (cum + h >= k) break;
                cum += h;
            }
            if (bin < 0) bin = 0;
            sh_pref = (prefix << 8) | (unsigned)bin;
            sh_k = k - cum;
        }
        __syncthreads();
        prefix = sh_pref; k = sh_k;
        __syncthreads();
    }
    unsigned T = prefix;
    if (t == 0) { cntGT = 0; eqcnt = 0; }
    __syncthreads();
    for (int i = t; i < HWSZ; i += bd) {
        unsigned u = __float_as_uint(sc[i] + sc2[i]);
        u = (u & 0x80000000u) ? ~u : (u | 0x80000000u);
        if (u > T) {
            int p = atomicAdd(&cntGT, 1);
            if (p < NPTS) g_idx[b * NPTS + p] = i;
        } else if (u == T) {
            int e = atomicAdd(&eqcnt, 1);
            if (e < 1024) eqbuf[e] = i;
        }
    }
    __syncthreads();
    if (t == 0) {
        int need = k;
        int base = cntGT;
        int ec = eqcnt; if (ec > 1024) ec = 1024;
        if (ec > need) {
            for (int a = 1; a < ec; ++a) {
                int v = eqbuf[a]; int jj = a - 1;
                while (jj >= 0 && eqbuf[jj] > v) { eqbuf[jj + 1] = eqbuf[jj]; --jj; }
                eqbuf[jj + 1] = v;
            }
        }
        for (int e = 0; e < need && e < ec && base + e < NPTS; ++e)
            g_idx[b * NPTS + base + e] = eqbuf[e];
    }
}

// ================= kernel 3: overlapped double-plane pooling =================
// One block per (b,c). Both planes issued via cp.async up front; pool xm while
// xa streams. Pooling = thread-per-patch (single pass, 500 of 512 threads),
// identical arithmetic to the proven round-5 version.
__global__ void __launch_bounds__(512) k3_pool(const float* __restrict__ xm,
                                               const float* __restrict__ xa) {
    extern __shared__ float sp[];            // [2][HWSZ], then int s_hw[512]
    int* s_hw = (int*)(sp + 2 * HWSZ);
    int c = blockIdx.x, b = blockIdx.y, t = threadIdx.x;

    const float* pm = xm + (size_t)(b * CH + c) * HWSZ;
    const float* pa = xa + (size_t)(b * CH + c) * HWSZ;
    // plane 0 (xm): 4096 16B chunks over 512 threads
    #pragma unroll
    for (int i = 0; i < 8; ++i) {
        int idx = t + i * 512;
        cp16(&sp[idx * 4], pm + idx * 4);
    }
    CP_COMMIT();
    // plane 1 (xa)
    #pragma unroll
    for (int i = 0; i < 8; ++i) {
        int idx = t + i * 512;
        cp16(&sp[HWSZ + idx * 4], pa + idx * 4);
    }
    CP_COMMIT();

    if (t < NPTS) s_hw[t] = g_idx[b * NPTS + t];

    CP_WAIT1();          // xm plane landed
    __syncthreads();

    #pragma unroll
    for (int s = 0; s < 2; ++s) {
        const float* pl = sp + s * HWSZ;
        if (t < NPTS) {
            int hw = s_hw[t];
            int iy = hw >> 7, ix = hw & 127;
            float sum = 0.f, mx = -CUDART_INF_F;
            if (iy >= 3 && iy <= 124 && ix >= 3 && ix <= 124) {
                const float* base = pl + (iy - 3) * WW + (ix - 3);
                #pragma unroll
                for (int dy = 0; dy < 7; ++dy) {
                    #pragma unroll
                    for (int dx = 0; dx < 7; ++dx) {
                        float v = base[dy * WW + dx];
                        sum += v; mx = fmaxf(mx, v);
                    }
                }
            } else {
                #pragma unroll
                for (int dy = -3; dy <= 3; ++dy) {
                    int yy = iy + dy; float wy = 1.f;
                    if (yy < 0) { yy = 0; wy = 0.5f; } else if (yy > 127) { yy = 127; wy = 0.5f; }
                    #pragma unroll
                    for (int dx = -3; dx <= 3; ++dx) {
                        int xx = ix + dx; float wx = wy;
                        if (xx < 0) { xx = 0; wx *= 0.5f; } else if (xx > 127) { xx = 127; wx *= 0.5f; }
                        float v = pl[yy * WW + xx] * wx;
                        sum += v; mx = fmaxf(mx, v);
                    }
                }
            }
            float r = 0.5f * (sum * (1.f / 49.f) + mx);
            if (s == 0) {
                g_vmt[(b * CH + c) * NPAD + t] = r;
            } else {
                g_vat[(b * CH + c) * NPAD + t] = r;
                g_vaux[(b * NPAD + t) * CH + c] = r;
            }
        }
        if (s == 0) {
            CP_WAIT0();  // xa plane landed (mostly hidden under xm pooling)
            __syncthreads();
        }
    }
}

// ================= kernel 4: tf32 mma attention, 16-row tiles, 2 CTAs/SM =================
#define T_QT 0
#define T_S  6144
#define T_B  14464
#define T_VH 22912
#define T_TOT 27136

__global__ void __launch_bounds__(512, 2)
k4_attn(const float* __restrict__ fc1w, const float* __restrict__ fc1b,
        const float* __restrict__ fc2w, const float* __restrict__ fc2b,
        const float* __restrict__ pw,   const float* __restrict__ pb,
        float* __restrict__ out) {
    extern __shared__ float sm[];
    float* Qt = sm + T_QT;
    float* S  = sm + T_S;
    float* Bf = sm + T_B;
    float* Vh = sm + T_VH;

    const int t = threadIdx.x, lane = t & 31, w = t >> 5;
    const int gid = lane >> 2, tig = lane & 3;
    const int b = blockIdx.y;
    const int r0 = blockIdx.x * 16;
    const int nrows = min(16, NPTS - r0);

    // ---- stage Q [k][r] pitch 24 (raw fp32 as tf32) ----
    for (int idx4 = t; idx4 < 1024; idx4 += 512) {
        int k = idx4 >> 2, i4 = (idx4 & 3) * 4;
        float4 v = *reinterpret_cast<const float4*>(&g_vmt[(b * CH + k) * NPAD + r0 + i4]);
        *reinterpret_cast<float4*>(&Qt[k * 24 + i4]) = v;
    }

    // ================= GEMM1: S[16][512] = Q[16][256] * K^T, scaled 1/16 =================
    {
        float dq[4][4] = {};
        const int ntb = w * 4;
        #pragma unroll
        for (int ii = 0; ii < 2; ++ii) {
            int op = t + ii * 512;
            int row = op >> 7, ch = op & 127;
            cp16(&Bf[row * 520 + ch * 4], &g_vat[(size_t)(b * CH + row) * NPAD + ch * 4]);
        }
        CP_COMMIT();
        for (int s = 0; s < 32; ++s) {
            if (s + 1 < 32) {
                int kbase = 8 * (s + 1);
                int bufo = ((s + 1) & 1) * 4160;
                #pragma unroll
                for (int ii = 0; ii < 2; ++ii) {
                    int op = t + ii * 512;
                    int row = op >> 7, ch = op & 127;
                    cp16(&Bf[bufo + row * 520 + ch * 4],
                         &g_vat[(size_t)(b * CH + kbase + row) * NPAD + ch * 4]);
                }
                CP_COMMIT();
                CP_WAIT1();
            } else {
                CP_WAIT0();
            }
            __syncthreads();
            const uint32_t* KS  = (const uint32_t*)&Bf[(s & 1) * 4160];
            const uint32_t* QtU = (const uint32_t*)Qt;
            int kg = 8 * s;
            uint32_t A[4];
            A[0] = QtU[(kg + tig) * 24 + gid];
            A[1] = QtU[(kg + tig) * 24 + gid + 8];
            A[2] = QtU[(kg + tig + 4) * 24 + gid];
            A[3] = QtU[(kg + tig + 4) * 24 + gid + 8];
            #pragma unroll
            for (int j = 0; j < 4; ++j) {
                int n0 = (ntb + j) * 8 + gid;
                uint32_t B[2];
                B[0] = KS[tig * 520 + n0];
                B[1] = KS[(tig + 4) * 520 + n0];
                mma8(dq[j], A, B);
            }
            __syncthreads();
        }
        #pragma unroll
        for (int j = 0; j < 4; ++j) {
            int n0 = (ntb + j) * 8 + 2 * tig;
            S[gid * 520 + n0]           = dq[j][0] * 0.0625f;
            S[gid * 520 + n0 + 1]       = dq[j][1] * 0.0625f;
            S[(gid + 8) * 520 + n0]     = dq[j][2] * 0.0625f;
            S[(gid + 8) * 520 + n0 + 1] = dq[j][3] * 0.0625f;
        }
        __syncthreads();
    }

    // ================= softmax (one row per warp; m>=500 zeroed) =================
    {
        int r = w;
        float mxv = -CUDART_INF_F;
        for (int m = lane; m < NPTS; m += 32) mxv = fmaxf(mxv, S[r * 520 + m]);
        #pragma unroll
        for (int o = 16; o; o >>= 1) mxv = fmaxf(mxv, __shfl_xor_sync(0xffffffffu, mxv, o));
        float sum = 0.f;
        for (int m = lane; m < NPTS; m += 32) {
            float e = __expf(S[r * 520 + m] - mxv);
            S[r * 520 + m] = e;
            sum += e;
        }
        #pragma unroll
        for (int o = 16; o; o >>= 1) sum += __shfl_xor_sync(0xffffffffu, sum, o);
        float inv = 1.f / sum;
        for (int m = lane; m < 512; m += 32) {
            float v = (m < NPTS) ? S[r * 520 + m] * inv : 0.f;
            S[r * 520 + m] = v;
        }
    }
    __syncthreads();

    // ================= GEMM2: Vh[16][256] = P[16][512] * V[512][256] =================
    {
        float dv[2][4] = {};
        const int ntb2 = w * 2;
        #pragma unroll
        for (int ii = 0; ii < 2; ++ii) {
            int op = t + ii * 512;
            int row = op >> 6, ch = op & 63;
            cp16(&Bf[row * 264 + ch * 4], &g_vaux[(size_t)(b * NPAD + row) * CH + ch * 4]);
        }
        CP_COMMIT();
        for (int s = 0; s < 32; ++s) {
            if (s + 1 < 32) {
                int mb = 16 * (s + 1);
                int bufo = ((s + 1) & 1) * 4224;
                #pragma unroll
                for (int ii = 0; ii < 2; ++ii) {
                    int op = t + ii * 512;
                    int row = op >> 6, ch = op & 63;
                    cp16(&Bf[bufo + row * 264 + ch * 4],
                         &g_vaux[(size_t)(b * NPAD + mb + row) * CH + ch * 4]);
                }
                CP_COMMIT();
                CP_WAIT1();
            } else {
                CP_WAIT0();
            }
            __syncthreads();
            const uint32_t* VS = (const uint32_t*)&Bf[(s & 1) * 4224];
            const uint32_t* PU = (const uint32_t*)S;
            #pragma unroll
            for (int kk = 0; kk < 2; ++kk) {
                int k0 = 16 * s + 8 * kk;
                uint32_t A[4];
                A[0] = PU[gid * 520 + k0 + tig];
                A[1] = PU[(gid + 8) * 520 + k0 + tig];
                A[2] = PU[gid * 520 + k0 + tig + 4];
                A[3] = PU[(gid + 8) * 520 + k0 + tig + 4];
                #pragma unroll
                for (int j = 0; j < 2; ++j) {
                    int n0 = (ntb2 + j) * 8 + gid;
                    uint32_t B[2];
                    B[0] = VS[(8 * kk + tig) * 264 + n0];
                    B[1] = VS[(8 * kk + tig + 4) * 264 + n0];
                    mma8(dv[j], A, B);
                }
            }
            __syncthreads();
        }
        #pragma unroll
        for (int j = 0; j < 2; ++j) {
            int n0 = (ntb2 + j) * 8 + 2 * tig;
            Vh[gid * 264 + n0]           = dv[j][0];
            Vh[gid * 264 + n0 + 1]       = dv[j][1];
            Vh[(gid + 8) * 264 + n0]     = dv[j][2];
            Vh[(gid + 8) * 264 + n0 + 1] = dv[j][3];
        }
        __syncthreads();
    }

    // ================= gated fusion MLP (fp32 exact) =================
    float* W1p = Bf;            // [256][32] interleaved (W1a,W1b)
    float* Vf  = S;             // [16][264] fused result (P dead)
    float* W2s = S + 4224;      // [16][256]
    for (int idx = t; idx < 4096; idx += 512) {
        int k = idx >> 4, j = idx & 15;
        float wa = fc1w[idx];
        float wb = fc1w[4096 + idx];
        float wc = fc1w[8192 + idx];
        W1p[k * 32 + 2 * j]     = wa + wc;
        W1p[k * 32 + 2 * j + 1] = wb - wc;
    }
    __syncthreads();
    for (int idx = t; idx < 4096; idx += 512) W2s[idx] = fc2w[idx];
    __syncthreads();

    int jl = lane & 15, half = lane >> 4;
    float hreg;
    {
        int r = w;
        u64 hp = pk2(0.f, 0.f);
        int k0 = half * 128;
        #pragma unroll 4
        for (int k = k0; k < k0 + 128; ++k) {
            float vm = Qt[k * 24 + r];
            float vh = Vh[r * 264 + k];
            u64 wv = *reinterpret_cast<const u64*>(&W1p[k * 32 + 2 * jl]);
            hp = f2fma(pk2(vm, vh), wv, hp);
        }
        float hx, hy; upk2(hx, hy, hp);
        float h = hx + hy;
        h += __shfl_xor_sync(0xffffffffu, h, 16);
        h += fc1b[jl];
        hreg = fmaxf(h, 0.f);
    }
    {
        int r = w;
        for (int cb = 0; cb < 256; cb += 32) {
            int c = cb + lane;
            float gg = fc2b[c];
            #pragma unroll
            for (int jj = 0; jj < 16; ++jj)
                gg += __shfl_sync(0xffffffffu, hreg, jj) * W2s[jj * 256 + c];
            gg = 1.f / (1.f + __expf(-gg));
            float vm = Qt[c * 24 + r];
            float vh = Vh[r * 264 + c];
            Vf[r * 264 + c] = vm + gg * (vm - vh);
        }
    }
    __syncthreads();

    // ================= GEMM3: v_inj = Vf[16][256] * proj_w[256][256]; scatter =================
    {
        float dp[2][4] = {};
        const int ntb3 = w * 2;
        #pragma unroll
        for (int ii = 0; ii < 2; ++ii) {
            int op = t + ii * 512;
            int row = op >> 6, ch = op & 63;
            cp16(&Bf[row * 264 + ch * 4], &pw[(size_t)row * 256 + ch * 4]);
        }
        CP_COMMIT();
        for (int s = 0; s < 16; ++s) {
            if (s + 1 < 16) {
                int kbse = 16 * (s + 1);
                int bufo = ((s + 1) & 1) * 4224;
                #pragma unroll
                for (int ii = 0; ii < 2; ++ii) {
                    int op = t + ii * 512;
                    int row = op >> 6, ch = op & 63;
                    cp16(&Bf[bufo + row * 264 + ch * 4],
                         &pw[(size_t)(kbse + row) * 256 + ch * 4]);
                }
                CP_COMMIT();
                CP_WAIT1();
            } else {
                CP_WAIT0();
            }
            __syncthreads();
            const uint32_t* WS = (const uint32_t*)&Bf[(s & 1) * 4224];
            const uint32_t* FU = (const uint32_t*)Vf;
            #pragma unroll
            for (int kk = 0; kk < 2; ++kk) {
                int k0 = 16 * s + 8 * kk;
                uint32_t A[4];
                A[0] = FU[gid * 264 + k0 + tig];
                A[1] = FU[(gid + 8) * 264 + k0 + tig];
                A[2] = FU[gid * 264 + k0 + tig + 4];
                A[3] = FU[(gid + 8) * 264 + k0 + tig + 4];
                #pragma unroll
                for (int j = 0; j < 2; ++j) {
                    int n0 = (ntb3 + j) * 8 + gid;
                    uint32_t B[2];
                    B[0] = WS[(8 * kk + tig) * 264 + n0];
                    B[1] = WS[(8 * kk + tig + 4) * 264 + n0];
                    mma8(dp[j], A, B);
                }
            }
            __syncthreads();
        }
        int hw0 = (gid < nrows)     ? g_idx[b * NPTS + r0 + gid]     : -1;
        int hw1 = (gid + 8 < nrows) ? g_idx[b * NPTS + r0 + gid + 8] : -1;
        #pragma unroll
        for (int j = 0; j < 2; ++j) {
            int c = (ntb3 + j) * 8 + 2 * tig;
            float pb0 = pb[c], pb1 = pb[c + 1];
            if (hw0 >= 0) {
                float* o0 = out + (size_t)(b * CH + c) * HWSZ + hw0;
                o0[0]    += dp[j][0] + pb0;
                o0[HWSZ] += dp[j][1] + pb1;
            }
            if (hw1 >= 0) {
                float* o1 = out + (size_t)(b * CH + c) * HWSZ + hw1;
                o1[0]    += dp[j][2] + pb0;
                o1[HWSZ] += dp[j][3] + pb1;
            }
        }
    }
}

// ================= launch =================
extern "C" void kernel_launch(void* const* d_in, const int* in_sizes, int n_in,
                              void* d_out, int out_size) {
    const float* xm   = (const float*)d_in[0];
    const float* xa   = (const float*)d_in[1];
    const float* sw   = (const float*)d_in[2];
    const float* fc1w = (const float*)d_in[4];
    const float* fc1b = (const float*)d_in[5];
    const float* fc2w = (const float*)d_in[6];
    const float* fc2b = (const float*)d_in[7];
    const float* pw   = (const float*)d_in[8];
    const float* pb   = (const float*)d_in[9];
    float* out = (float*)d_out;

    const int K3_SMEM = 2 * HWSZ * 4 + NPAD * 4;   // 133120 B
    const int K4_SMEM = T_TOT * 4;                 // 108544 B
    cudaFuncSetAttribute(k3_pool, cudaFuncAttributeMaxDynamicSharedMemorySize, K3_SMEM);
    cudaFuncSetAttribute(k4_attn, cudaFuncAttributeMaxDynamicSharedMemorySize, K4_SMEM);

    k1_copy_score<<<dim3(512, 2), 256>>>(xm, sw, out);
    k2_topk<<<BATCH, 512>>>();
    k3_pool<<<dim3(CH, BATCH), 512, K3_SMEM>>>(xm, xa);
    k4_attn<<<dim3(32, BATCH), 512, K4_SMEM>>>(fc1w, fc1b, fc2w, fc2b, pw, pb, out);
}

// round 13
// speedup vs baseline: 1.0229x; 1.0002x over previous
#include <cuda_runtime.h>
#include <math_constants.h>
#include <stdint.h>

#define BATCH 8
#define CH 256
#define HH 128
#define WW 128
#define HWSZ 16384
#define NPTS 500
#define NPAD 512
#define NHID 16

typedef unsigned long long u64;

// ---------------- scratch ----------------
__device__ float g_score [BATCH * HWSZ];
__device__ float g_spart2[BATCH * HWSZ];
__device__ int   g_idx[BATCH * NPTS];
__device__ float g_vmt [BATCH * CH * NPAD];   // v_main transposed [b][c][n], zero-padded
__device__ float g_vat [BATCH * CH * NPAD];   // v_aux  transposed [b][c][n], zero-padded
__device__ float g_vaux[BATCH * NPAD * CH];   // v_aux row-major [b][n][c], rows >=500 zero

// ---------------- f32x2 helpers (fc1 path) ----------------
__device__ __forceinline__ u64 pk2(float x, float y) {
    u64 d; asm("mov.b64 %0, {%1, %2};" : "=l"(d) : "f"(x), "f"(y)); return d;
}
__device__ __forceinline__ void upk2(float& x, float& y, u64 d) {
    asm("mov.b64 {%0, %1}, %2;" : "=f"(x), "=f"(y) : "l"(d));
}
__device__ __forceinline__ u64 f2fma(u64 a, u64 b, u64 c) {
    u64 d; asm("fma.rn.f32x2 %0, %1, %2, %3;" : "=l"(d) : "l"(a), "l"(b), "l"(c)); return d;
}

// ---------------- tensor-core + cp.async helpers ----------------
__device__ __forceinline__ void mma8(float* d, const uint32_t* a, const uint32_t* b) {
    asm volatile(
        "mma.sync.aligned.m16n8k8.row.col.f32.tf32.tf32.f32 "
        "{%0,%1,%2,%3},{%4,%5,%6,%7},{%8,%9},{%0,%1,%2,%3};"
        : "+f"(d[0]), "+f"(d[1]), "+f"(d[2]), "+f"(d[3])
        : "r"(a[0]), "r"(a[1]), "r"(a[2]), "r"(a[3]), "r"(b[0]), "r"(b[1]));
}
__device__ __forceinline__ void cp16(const void* smem_dst, const float* gsrc) {
    uint32_t d;
    asm("{ .reg .u64 tt; cvta.to.shared.u64 tt, %1; cvt.u32.u64 %0, tt; }" : "=r"(d) : "l"(smem_dst));
    asm volatile("cp.async.cg.shared.global [%0], [%1], 16;" :: "r"(d), "l"(gsrc));
}
#define CP_COMMIT() asm volatile("cp.async.commit_group;")
#define CP_WAIT3()  asm volatile("cp.async.wait_group 3;")
#define CP_WAIT1()  asm volatile("cp.async.wait_group 1;")
#define CP_WAIT0()  asm volatile("cp.async.wait_group 0;")

// ================= kernel 1: fused copy + scorer, register-only partials =================
__global__ void __launch_bounds__(256) k1_copy_score(const float* __restrict__ xm,
                                                     const float* __restrict__ sw,
                                                     float* __restrict__ out) {
    __shared__ float s_w[128];
    int t = threadIdx.x, s = blockIdx.y;
    if (t < 128) s_w[t] = sw[s * 128 + t];
    __syncthreads();

    int p  = blockIdx.x * 256 + t;
    int b  = p >> 14;
    int hw = p & (HWSZ - 1);
    const float* src = xm + (size_t)(b * CH + s * 128) * HWSZ + hw;
    float*       dst = out + (size_t)(b * CH + s * 128) * HWSZ + hw;

    float a = 0.f;
    #pragma unroll 8
    for (int c = 0; c < 128; ++c) {
        float v = src[(size_t)c * HWSZ];
        dst[(size_t)c * HWSZ] = v;
        a += v * s_w[c];
    }
    (s == 0 ? g_score : g_spart2)[p] = a;
}

// ================= kernel 2: exact top-500 per batch via radix select =================
__global__ void k2_topk() {
    __shared__ unsigned hist[256];
    __shared__ unsigned sh_pref;
    __shared__ int sh_k;
    __shared__ int cntGT, eqcnt;
    __shared__ int eqbuf[1024];

    int b = blockIdx.x, t = threadIdx.x, bd = blockDim.x;
    const float* sc  = g_score  + b * HWSZ;
    const float* sc2 = g_spart2 + b * HWSZ;

    unsigned prefix = 0;
    int k = NPTS;
    for (int byte = 3; byte >= 0; --byte) {
        if (t < 256) hist[t] = 0;
        __syncthreads();
        int shamt = byte * 8;
        for (int i = t; i < HWSZ; i += bd) {
            unsigned u = __float_as_uint(sc[i] + sc2[i]);
            u = (u & 0x80000000u) ? ~u : (u | 0x80000000u);
            bool m = (byte == 3) || ((u >> (shamt + 8)) == prefix);
            if (m) atomicAdd(&hist[(u >> shamt) & 255u], 1u);
        }
        __syncthreads();
        if (t == 0) {
            int cum = 0, bin;
            for (bin = 255; bin >= 0; --bin) {
                int h = (int)hist[bin];
                if (cum + h >= k) break;
                cum += h;
            }
            if (bin < 0) bin = 0;
            sh_pref = (prefix << 8) | (unsigned)bin;
            sh_k = k - cum;
        }
        __syncthreads();
        prefix = sh_pref; k = sh_k;
        __syncthreads();
    }
    unsigned T = prefix;
    if (t == 0) { cntGT = 0; eqcnt = 0; }
    __syncthreads();
    for (int i = t; i < HWSZ; i += bd) {
        unsigned u = __float_as_uint(sc[i] + sc2[i]);
        u = (u & 0x80000000u) ? ~u : (u | 0x80000000u);
        if (u > T) {
            int p = atomicAdd(&cntGT, 1);
            if (p < NPTS) g_idx[b * NPTS + p] = i;
        } else if (u == T) {
            int e = atomicAdd(&eqcnt, 1);
            if (e < 1024) eqbuf[e] = i;
        }
    }
    __syncthreads();
    if (t == 0) {
        int need = k;
        int base = cntGT;
        int ec = eqcnt; if (ec > 1024) ec = 1024;
        if (ec > need) {
            for (int a = 1; a < ec; ++a) {
                int v = eqbuf[a]; int jj = a - 1;
                while (jj >= 0 && eqbuf[jj] > v) { eqbuf[jj + 1] = eqbuf[jj]; --jj; }
                eqbuf[jj + 1] = v;
            }
        }
        for (int e = 0; e < need && e < ec && base + e < NPTS; ++e)
            g_idx[b * NPTS + base + e] = eqbuf[e];
    }
}

// ================= kernel 3: overlapped double-plane pooling =================
__global__ void __launch_bounds__(512) k3_pool(const float* __restrict__ xm,
                                               const float* __restrict__ xa) {
    extern __shared__ float sp[];            // [2][HWSZ], then int s_hw[512]
    int* s_hw = (int*)(sp + 2 * HWSZ);
    int c = blockIdx.x, b = blockIdx.y, t = threadIdx.x;

    const float* pm = xm + (size_t)(b * CH + c) * HWSZ;
    const float* pa = xa + (size_t)(b * CH + c) * HWSZ;
    #pragma unroll
    for (int i = 0; i < 8; ++i) {
        int idx = t + i * 512;
        cp16(&sp[idx * 4], pm + idx * 4);
    }
    CP_COMMIT();
    #pragma unroll
    for (int i = 0; i < 8; ++i) {
        int idx = t + i * 512;
        cp16(&sp[HWSZ + idx * 4], pa + idx * 4);
    }
    CP_COMMIT();

    if (t < NPTS) s_hw[t] = g_idx[b * NPTS + t];

    CP_WAIT1();
    __syncthreads();

    #pragma unroll
    for (int s = 0; s < 2; ++s) {
        const float* pl = sp + s * HWSZ;
        if (t < NPTS) {
            int hw = s_hw[t];
            int iy = hw >> 7, ix = hw & 127;
            float sum = 0.f, mx = -CUDART_INF_F;
            if (iy >= 3 && iy <= 124 && ix >= 3 && ix <= 124) {
                const float* base = pl + (iy - 3) * WW + (ix - 3);
                #pragma unroll
                for (int dy = 0; dy < 7; ++dy) {
                    #pragma unroll
                    for (int dx = 0; dx < 7; ++dx) {
                        float v = base[dy * WW + dx];
                        sum += v; mx = fmaxf(mx, v);
                    }
                }
            } else {
                #pragma unroll
                for (int dy = -3; dy <= 3; ++dy) {
                    int yy = iy + dy; float wy = 1.f;
                    if (yy < 0) { yy = 0; wy = 0.5f; } else if (yy > 127) { yy = 127; wy = 0.5f; }
                    #pragma unroll
                    for (int dx = -3; dx <= 3; ++dx) {
                        int xx = ix + dx; float wx = wy;
                        if (xx < 0) { xx = 0; wx *= 0.5f; } else if (xx > 127) { xx = 127; wx *= 0.5f; }
                        float v = pl[yy * WW + xx] * wx;
                        sum += v; mx = fmaxf(mx, v);
                    }
                }
            }
            float r = 0.5f * (sum * (1.f / 49.f) + mx);
            if (s == 0) {
                g_vmt[(b * CH + c) * NPAD + t] = r;
            } else {
                g_vat[(b * CH + c) * NPAD + t] = r;
                g_vaux[(b * NPAD + t) * CH + c] = r;
            }
        }
        if (s == 0) {
            CP_WAIT0();
            __syncthreads();
        }
    }
}

// ================= kernel 4: tf32 mma attention, 32-row tiles, 3-deep cp.async =================
// smem (floats):
//  Qt [256][40]                 @ 0      (10240)
//  S  [32][520] (S/P; later Vf[32][264]) @ 10240 (16640)
//  Bf 4 x 4224 ring (K 8x520 | V/W 16x264 | later W1p+W2s) @ 26880 (16896)
//  Vh [32][264]                 @ 43776  (8448)
#define T_QT 0
#define T_S  10240
#define T_B  26880
#define T_VH 43776
#define T_TOT 52224
#define BSTR 4224

__global__ void __launch_bounds__(512, 1)
k4_attn(const float* __restrict__ fc1w, const float* __restrict__ fc1b,
        const float* __restrict__ fc2w, const float* __restrict__ fc2b,
        const float* __restrict__ pw,   const float* __restrict__ pb,
        float* __restrict__ out) {
    extern __shared__ float sm[];
    float* Qt = sm + T_QT;
    float* S  = sm + T_S;
    float* Bf = sm + T_B;
    float* Vh = sm + T_VH;

    const int t = threadIdx.x, lane = t & 31, w = t >> 5;
    const int gid = lane >> 2, tig = lane & 3;
    const int b = blockIdx.y;
    const int r0 = blockIdx.x * 32;
    const int nrows = min(32, NPTS - r0);

    // ---- stage Q [k][r] pitch 40 (raw fp32 as tf32) ----
    for (int idx4 = t; idx4 < 2048; idx4 += 512) {
        int k = idx4 >> 3, i4 = (idx4 & 7) * 4;
        float4 v = *reinterpret_cast<const float4*>(&g_vmt[(b * CH + k) * NPAD + r0 + i4]);
        *reinterpret_cast<float4*>(&Qt[k * 40 + i4]) = v;
    }

    // ================= GEMM1: S[32][512] = Q K^T / 16 ; 32 slices of 8 k-rows =================
    {
        float dq[2][4][4] = {};
        const int ntb = w * 4;
        // prologue: slices 0,1,2
        #pragma unroll
        for (int p = 0; p < 3; ++p) {
            #pragma unroll
            for (int ii = 0; ii < 2; ++ii) {
                int op = t + ii * 512;
                int row = op >> 7, ch = op & 127;
                cp16(&Bf[p * BSTR + row * 520 + ch * 4],
                     &g_vat[(size_t)(b * CH + p * 8 + row) * NPAD + ch * 4]);
            }
            CP_COMMIT();
        }
        for (int s = 0; s < 32; ++s) {
            if (s + 3 < 32) {
                int kbase = 8 * (s + 3);
                int bufo = ((s + 3) & 3) * BSTR;
                #pragma unroll
                for (int ii = 0; ii < 2; ++ii) {
                    int op = t + ii * 512;
                    int row = op >> 7, ch = op & 127;
                    cp16(&Bf[bufo + row * 520 + ch * 4],
                         &g_vat[(size_t)(b * CH + kbase + row) * NPAD + ch * 4]);
                }
            }
            CP_COMMIT();          // empty group at tail keeps wait_group 3 uniform
            CP_WAIT3();
            __syncthreads();
            const uint32_t* KS  = (const uint32_t*)&Bf[(s & 3) * BSTR];
            const uint32_t* QtU = (const uint32_t*)Qt;
            uint32_t A[2][4];
            int ka = (8 * s + tig) * 40;
            int kb = (8 * s + tig + 4) * 40;
            #pragma unroll
            for (int mt = 0; mt < 2; ++mt) {
                int r = mt * 16 + gid;
                A[mt][0] = QtU[ka + r];
                A[mt][1] = QtU[ka + r + 8];
                A[mt][2] = QtU[kb + r];
                A[mt][3] = QtU[kb + r + 8];
            }
            #pragma unroll
            for (int j = 0; j < 4; ++j) {
                int n0 = (ntb + j) * 8 + gid;
                uint32_t B[2];
                B[0] = KS[tig * 520 + n0];
                B[1] = KS[(tig + 4) * 520 + n0];
                mma8(dq[0][j], A[0], B);
                mma8(dq[1][j], A[1], B);
            }
            __syncthreads();
        }
        #pragma unroll
        for (int mt = 0; mt < 2; ++mt) {
            #pragma unroll
            for (int j = 0; j < 4; ++j) {
                int r = mt * 16 + gid;
                int n0 = (ntb + j) * 8 + 2 * tig;
                S[r * 520 + n0]           = dq[mt][j][0] * 0.0625f;
                S[r * 520 + n0 + 1]       = dq[mt][j][1] * 0.0625f;
                S[(r + 8) * 520 + n0]     = dq[mt][j][2] * 0.0625f;
                S[(r + 8) * 520 + n0 + 1] = dq[mt][j][3] * 0.0625f;
            }
        }
        __syncthreads();
    }

    // ================= softmax rows (normalized P in S; m>=500 zeroed) =================
    #pragma unroll
    for (int i = 0; i < 2; ++i) {
        int r = 2 * w + i;
        float mxv = -CUDART_INF_F;
        for (int m = lane; m < NPTS; m += 32) mxv = fmaxf(mxv, S[r * 520 + m]);
        #pragma unroll
        for (int o = 16; o; o >>= 1) mxv = fmaxf(mxv, __shfl_xor_sync(0xffffffffu, mxv, o));
        float sum = 0.f;
        for (int m = lane; m < NPTS; m += 32) {
            float e = __expf(S[r * 520 + m] - mxv);
            S[r * 520 + m] = e;
            sum += e;
        }
        #pragma unroll
        for (int o = 16; o; o >>= 1) sum += __shfl_xor_sync(0xffffffffu, sum, o);
        float inv = 1.f / sum;
        for (int m = lane; m < 512; m += 32) {
            float v = (m < NPTS) ? S[r * 520 + m] * inv : 0.f;
            S[r * 520 + m] = v;
        }
    }
    __syncthreads();

    // ================= GEMM2: Vh[32][256] = P[32][512] V[512][256] ; 32 slices of 16 m-rows ==========
    {
        float dv[2][2][4] = {};
        const int ntb2 = w * 2;
        #pragma unroll
        for (int p = 0; p < 3; ++p) {
            #pragma unroll
            for (int ii = 0; ii < 2; ++ii) {
                int op = t + ii * 512;
                int row = op >> 6, ch = op & 63;
                cp16(&Bf[p * BSTR + row * 264 + ch * 4],
                     &g_vaux[(size_t)(b * NPAD + p * 16 + row) * CH + ch * 4]);
            }
            CP_COMMIT();
        }
        for (int s = 0; s < 32; ++s) {
            if (s + 3 < 32) {
                int mb = 16 * (s + 3);
                int bufo = ((s + 3) & 3) * BSTR;
                #pragma unroll
                for (int ii = 0; ii < 2; ++ii) {
                    int op = t + ii * 512;
                    int row = op >> 6, ch = op & 63;
                    cp16(&Bf[bufo + row * 264 + ch * 4],
                         &g_vaux[(size_t)(b * NPAD + mb + row) * CH + ch * 4]);
                }
            }
            CP_COMMIT();
            CP_WAIT3();
            __syncthreads();
            const uint32_t* VS = (const uint32_t*)&Bf[(s & 3) * BSTR];
            const uint32_t* PU = (const uint32_t*)S;
            #pragma unroll
            for (int kk = 0; kk < 2; ++kk) {
                int k0 = 16 * s + 8 * kk;
                uint32_t A[2][4];
                #pragma unroll
                for (int mt = 0; mt < 2; ++mt) {
                    int r = mt * 16 + gid;
                    A[mt][0] = PU[r * 520 + k0 + tig];
                    A[mt][1] = PU[(r + 8) * 520 + k0 + tig];
                    A[mt][2] = PU[r * 520 + k0 + tig + 4];
                    A[mt][3] = PU[(r + 8) * 520 + k0 + tig + 4];
                }
                #pragma unroll
                for (int j = 0; j < 2; ++j) {
                    int n0 = (ntb2 + j) * 8 + gid;
                    uint32_t B[2];
                    B[0] = VS[(8 * kk + tig) * 264 + n0];
                    B[1] = VS[(8 * kk + tig + 4) * 264 + n0];
                    mma8(dv[0][j], A[0], B);
                    mma8(dv[1][j], A[1], B);
                }
            }
            __syncthreads();
        }
        #pragma unroll
        for (int mt = 0; mt < 2; ++mt) {
            #pragma unroll
            for (int j = 0; j < 2; ++j) {
                int r = mt * 16 + gid;
                int n0 = (ntb2 + j) * 8 + 2 * tig;
                Vh[r * 264 + n0]           = dv[mt][j][0];
                Vh[r * 264 + n0 + 1]       = dv[mt][j][1];
                Vh[(r + 8) * 264 + n0]     = dv[mt][j][2];
                Vh[(r + 8) * 264 + n0 + 1] = dv[mt][j][3];
            }
        }
        __syncthreads();
    }

    // ================= gated fusion MLP (fp32 exact) =================
    CP_WAIT0();
    float* W1p = Bf;            // [256][32] interleaved (W1a,W1b)
    float* Vf  = S;             // [32][264] fused result (P dead)
    float* W2s = Bf + 8192;     // [16][256]
    for (int idx = t; idx < 4096; idx += 512) {
        int k = idx >> 4, j = idx & 15;
        float wa = fc1w[idx];
        float wb = fc1w[4096 + idx];
        float wc = fc1w[8192 + idx];
        W1p[k * 32 + 2 * j]     = wa + wc;
        W1p[k * 32 + 2 * j + 1] = wb - wc;
    }
    for (int idx = t; idx < 4096; idx += 512) W2s[idx] = fc2w[idx];
    __syncthreads();

    int jl = lane & 15, half = lane >> 4;
    float hreg[2];
    #pragma unroll
    for (int i = 0; i < 2; ++i) {
        int r = 2 * w + i;
        u64 hp = pk2(0.f, 0.f);
        int k0 = half * 128;
        #pragma unroll 4
        for (int k = k0; k < k0 + 128; ++k) {
            float vm = Qt[k * 40 + r];
            float vh = Vh[r * 264 + k];
            u64 wv = *reinterpret_cast<const u64*>(&W1p[k * 32 + 2 * jl]);
            hp = f2fma(pk2(vm, vh), wv, hp);
        }
        float hx, hy; upk2(hx, hy, hp);
        float h = hx + hy;
        h += __shfl_xor_sync(0xffffffffu, h, 16);
        h += fc1b[jl];
        hreg[i] = fmaxf(h, 0.f);
    }
    #pragma unroll
    for (int i = 0; i < 2; ++i) {
        int r = 2 * w + i;
        for (int cb = 0; cb < 256; cb += 32) {
            int c = cb + lane;
            float gg = fc2b[c];
            #pragma unroll
            for (int jj = 0; jj < 16; ++jj)
                gg += __shfl_sync(0xffffffffu, hreg[i], jj) * W2s[jj * 256 + c];
            gg = 1.f / (1.f + __expf(-gg));
            float vm = Qt[c * 40 + r];
            float vh = Vh[r * 264 + c];
            Vf[r * 264 + c] = vm + gg * (vm - vh);
        }
    }
    __syncthreads();

    // ================= GEMM3: v_inj = Vf proj_w ; 16 slices of 16 k-rows ; scatter ==========
    {
        float dp[2][2][4] = {};
        const int ntb3 = w * 2;
        #pragma unroll
        for (int p = 0; p < 3; ++p) {
            #pragma unroll
            for (int ii = 0; ii < 2; ++ii) {
                int op = t + ii * 512;
                int row = op >> 6, ch = op & 63;
                cp16(&Bf[p * BSTR + row * 264 + ch * 4],
                     &pw[(size_t)(p * 16 + row) * 256 + ch * 4]);
            }
            CP_COMMIT();
        }
        for (int s = 0; s < 16; ++s) {
            if (s + 3 < 16) {
                int kbse = 16 * (s + 3);
                int bufo = ((s + 3) & 3) * BSTR;
                #pragma unroll
                for (int ii = 0; ii < 2; ++ii) {
                    int op = t + ii * 512;
                    int row = op >> 6, ch = op & 63;
                    cp16(&Bf[bufo + row * 264 + ch * 4],
                         &pw[(size_t)(kbse + row) * 256 + ch * 4]);
                }
            }
            CP_COMMIT();
            CP_WAIT3();
            __syncthreads();
            const uint32_t* WS = (const uint32_t*)&Bf[(s & 3) * BSTR];
            const uint32_t* FU = (const uint32_t*)Vf;
            #pragma unroll
            for (int kk = 0; kk < 2; ++kk) {
                int k0 = 16 * s + 8 * kk;
                uint32_t A[2][4];
                #pragma unroll
                for (int mt = 0; mt < 2; ++mt) {
                    int r = mt * 16 + gid;
                    A[mt][0] = FU[r * 264 + k0 + tig];
                    A[mt][1] = FU[(r + 8) * 264 + k0 + tig];
                    A[mt][2] = FU[r * 264 + k0 + tig + 4];
                    A[mt][3] = FU[(r + 8) * 264 + k0 + tig + 4];
                }
                #pragma unroll
                for (int j = 0; j < 2; ++j) {
                    int n0 = (ntb3 + j) * 8 + gid;
                    uint32_t B[2];
                    B[0] = WS[(8 * kk + tig) * 264 + n0];
                    B[1] = WS[(8 * kk + tig + 4) * 264 + n0];
                    mma8(dp[0][j], A[0], B);
                    mma8(dp[1][j], A[1], B);
                }
            }
            __syncthreads();
        }
        // scatter-add epilogue (indices unique per batch -> plain RMW)
        #pragma unroll
        for (int mt = 0; mt < 2; ++mt) {
            int r = mt * 16 + gid;
            int hw0 = (r < nrows)     ? g_idx[b * NPTS + r0 + r]     : -1;
            int hw1 = (r + 8 < nrows) ? g_idx[b * NPTS + r0 + r + 8] : -1;
            #pragma unroll
            for (int j = 0; j < 2; ++j) {
                int c = (ntb3 + j) * 8 + 2 * tig;
                float pb0 = pb[c], pb1 = pb[c + 1];
                if (hw0 >= 0) {
                    float* o0 = out + (size_t)(b * CH + c) * HWSZ + hw0;
                    o0[0]    += dp[mt][j][0] + pb0;
                    o0[HWSZ] += dp[mt][j][1] + pb1;
                }
                if (hw1 >= 0) {
                    float* o1 = out + (size_t)(b * CH + c) * HWSZ + hw1;
                    o1[0]    += dp[mt][j][2] + pb0;
                    o1[HWSZ] += dp[mt][j][3] + pb1;
                }
            }
        }
    }
}

// ================= launch =================
extern "C" void kernel_launch(void* const* d_in, const int* in_sizes, int n_in,
                              void* d_out, int out_size) {
    const float* xm   = (const float*)d_in[0];
    const float* xa   = (const float*)d_in[1];
    const float* sw   = (const float*)d_in[2];
    const float* fc1w = (const float*)d_in[4];
    const float* fc1b = (const float*)d_in[5];
    const float* fc2w = (const float*)d_in[6];
    const float* fc2b = (const float*)d_in[7];
    const float* pw   = (const float*)d_in[8];
    const float* pb   = (const float*)d_in[9];
    float* out = (float*)d_out;

    const int K3_SMEM = 2 * HWSZ * 4 + NPAD * 4;   // 133120 B
    const int K4_SMEM = T_TOT * 4;                 // 208896 B
    cudaFuncSetAttribute(k3_pool, cudaFuncAttributeMaxDynamicSharedMemorySize, K3_SMEM);
    cudaFuncSetAttribute(k4_attn, cudaFuncAttributeMaxDynamicSharedMemorySize, K4_SMEM);

    k1_copy_score<<<dim3(512, 2), 256>>>(xm, sw, out);
    k2_topk<<<BATCH, 512>>>();
    k3_pool<<<dim3(CH, BATCH), 512, K3_SMEM>>>(xm, xa);
    k4_attn<<<dim3(16, BATCH), 512, K4_SMEM>>>(fc1w, fc1b, fc2w, fc2b, pw, pb, out);
}

// round 14
// speedup vs baseline: 1.0650x; 1.0411x over previous
#include <cuda_runtime.h>
#include <math_constants.h>
#include <stdint.h>

#define BATCH 8
#define CH 256
#define HH 128
#define WW 128
#define HWSZ 16384
#define NPTS 500
#define NPAD 512
#define NHID 16

typedef unsigned long long u64;

// ---------------- scratch ----------------
__device__ float g_score [BATCH * HWSZ];
__device__ float g_spart2[BATCH * HWSZ];
__device__ int   g_idx[BATCH * NPTS];
__device__ float g_vmt [BATCH * CH * NPAD];   // v_main transposed [b][c][n], zero-padded
__device__ float g_vat [BATCH * CH * NPAD];   // v_aux  transposed [b][c][n], zero-padded
__device__ float g_vaux[BATCH * NPAD * CH];   // v_aux row-major [b][n][c], rows >=500 zero

// ---------------- f32x2 helpers (fc1 path) ----------------
__device__ __forceinline__ u64 pk2(float x, float y) {
    u64 d; asm("mov.b64 %0, {%1, %2};" : "=l"(d) : "f"(x), "f"(y)); return d;
}
__device__ __forceinline__ void upk2(float& x, float& y, u64 d) {
    asm("mov.b64 {%0, %1}, %2;" : "=f"(x), "=f"(y) : "l"(d));
}
__device__ __forceinline__ u64 f2fma(u64 a, u64 b, u64 c) {
    u64 d; asm("fma.rn.f32x2 %0, %1, %2, %3;" : "=l"(d) : "l"(a), "l"(b), "l"(c)); return d;
}

// ---------------- tensor-core + cp.async helpers ----------------
__device__ __forceinline__ void mma8(float* d, const uint32_t* a, const uint32_t* b) {
    asm volatile(
        "mma.sync.aligned.m16n8k8.row.col.f32.tf32.tf32.f32 "
        "{%0,%1,%2,%3},{%4,%5,%6,%7},{%8,%9},{%0,%1,%2,%3};"
        : "+f"(d[0]), "+f"(d[1]), "+f"(d[2]), "+f"(d[3])
        : "r"(a[0]), "r"(a[1]), "r"(a[2]), "r"(a[3]), "r"(b[0]), "r"(b[1]));
}
__device__ __forceinline__ void cp16(const void* smem_dst, const float* gsrc) {
    uint32_t d;
    asm("{ .reg .u64 tt; cvta.to.shared.u64 tt, %1; cvt.u32.u64 %0, tt; }" : "=r"(d) : "l"(smem_dst));
    asm volatile("cp.async.cg.shared.global [%0], [%1], 16;" :: "r"(d), "l"(gsrc));
}
#define CP_COMMIT() asm volatile("cp.async.commit_group;")
#define CP_WAIT3()  asm volatile("cp.async.wait_group 3;")
#define CP_WAIT1()  asm volatile("cp.async.wait_group 1;")
#define CP_WAIT0()  asm volatile("cp.async.wait_group 0;")

// ================= kernel 1: fused copy + scorer, register-only partials =================
__global__ void __launch_bounds__(256) k1_copy_score(const float* __restrict__ xm,
                                                     const float* __restrict__ sw,
                                                     float* __restrict__ out) {
    __shared__ float s_w[128];
    int t = threadIdx.x, s = blockIdx.y;
    if (t < 128) s_w[t] = sw[s * 128 + t];
    __syncthreads();

    int p  = blockIdx.x * 256 + t;
    int b  = p >> 14;
    int hw = p & (HWSZ - 1);
    const float* src = xm + (size_t)(b * CH + s * 128) * HWSZ + hw;
    float*       dst = out + (size_t)(b * CH + s * 128) * HWSZ + hw;

    float a = 0.f;
    #pragma unroll 8
    for (int c = 0; c < 128; ++c) {
        float v = src[(size_t)c * HWSZ];
        dst[(size_t)c * HWSZ] = v;
        a += v * s_w[c];
    }
    (s == 0 ? g_score : g_spart2)[p] = a;
}

// ================= kernel 2: exact top-500 per batch via radix select =================
__global__ void k2_topk() {
    __shared__ unsigned hist[256];
    __shared__ unsigned sh_pref;
    __shared__ int sh_k;
    __shared__ int cntGT, eqcnt;
    __shared__ int eqbuf[1024];

    int b = blockIdx.x, t = threadIdx.x, bd = blockDim.x;
    const float* sc  = g_score  + b * HWSZ;
    const float* sc2 = g_spart2 + b * HWSZ;

    unsigned prefix = 0;
    int k = NPTS;
    for (int byte = 3; byte >= 0; --byte) {
        if (t < 256) hist[t] = 0;
        __syncthreads();
        int shamt = byte * 8;
        for (int i = t; i < HWSZ; i += bd) {
            unsigned u = __float_as_uint(sc[i] + sc2[i]);
            u = (u & 0x80000000u) ? ~u : (u | 0x80000000u);
            bool m = (byte == 3) || ((u >> (shamt + 8)) == prefix);
            if (m) atomicAdd(&hist[(u >> shamt) & 255u], 1u);
        }
        __syncthreads();
        if (t == 0) {
            int cum = 0, bin;
            for (bin = 255; bin >= 0; --bin) {
                int h = (int)hist[bin];
                if (cum + h >= k) break;
                cum += h;
            }
            if (bin < 0) bin = 0;
            sh_pref = (prefix << 8) | (unsigned)bin;
            sh_k = k - cum;
        }
        __syncthreads();
        prefix = sh_pref; k = sh_k;
        __syncthreads();
    }
    unsigned T = prefix;
    if (t == 0) { cntGT = 0; eqcnt = 0; }
    __syncthreads();
    for (int i = t; i < HWSZ; i += bd) {
        unsigned u = __float_as_uint(sc[i] + sc2[i]);
        u = (u & 0x80000000u) ? ~u : (u | 0x80000000u);
        if (u > T) {
            int p = atomicAdd(&cntGT, 1);
            if (p < NPTS) g_idx[b * NPTS + p] = i;
        } else if (u == T) {
            int e = atomicAdd(&eqcnt, 1);
            if (e < 1024) eqbuf[e] = i;
        }
    }
    __syncthreads();
    if (t == 0) {
        int need = k;
        int base = cntGT;
        int ec = eqcnt; if (ec > 1024) ec = 1024;
        if (ec > need) {
            for (int a = 1; a < ec; ++a) {
                int v = eqbuf[a]; int jj = a - 1;
                while (jj >= 0 && eqbuf[jj] > v) { eqbuf[jj + 1] = eqbuf[jj]; --jj; }
                eqbuf[jj + 1] = v;
            }
        }
        for (int e = 0; e < need && e < ec && base + e < NPTS; ++e)
            g_idx[b * NPTS + base + e] = eqbuf[e];
    }
}

// ================= kernel 3: half-plane pooling, 6 CTAs/SM =================
// grid (256, 8, 4): z = half*2 + src. Block loads rows [0,66] or [61,127] of one
// plane (67 rows, pitch 132) and pools patches whose center iy falls in its half
// (the +/-3 halo incl. clamps stays inside the loaded range). Thread-per-patch.
#define K3ROWS 67
#define K3PITCH 132

__global__ void __launch_bounds__(256) k3_pool(const float* __restrict__ xm,
                                               const float* __restrict__ xa) {
    extern __shared__ float sp[];            // [K3ROWS][K3PITCH], then int s_hw[512]
    int* s_hw = (int*)(sp + K3ROWS * K3PITCH);
    int c = blockIdx.x, b = blockIdx.y;
    int src = blockIdx.z & 1, half = blockIdx.z >> 1;
    int t = threadIdx.x;
    int r0 = half ? 61 : 0;

    const float* pg = (src == 0 ? xm : xa) + (size_t)(b * CH + c) * HWSZ + r0 * WW;
    for (int idx = t; idx < K3ROWS * 32; idx += 256) {
        int row = idx >> 5, col = idx & 31;
        cp16(&sp[row * K3PITCH + col * 4], pg + row * WW + col * 4);
    }
    CP_COMMIT();
    for (int i = t; i < NPTS; i += 256) s_hw[i] = g_idx[b * NPTS + i];
    CP_WAIT0();
    __syncthreads();

    for (int p = t; p < NPTS; p += 256) {
        int hw = s_hw[p];
        int iy = hw >> 7, ix = hw & 127;
        bool mine = half ? (iy >= 64) : (iy <= 63);
        if (!mine) continue;
        float sum = 0.f, mx = -CUDART_INF_F;
        if (iy >= 3 && iy <= 124 && ix >= 3 && ix <= 124) {
            const float* base = sp + (iy - 3 - r0) * K3PITCH + (ix - 3);
            #pragma unroll
            for (int dy = 0; dy < 7; ++dy) {
                #pragma unroll
                for (int dx = 0; dx < 7; ++dx) {
                    float v = base[dy * K3PITCH + dx];
                    sum += v; mx = fmaxf(mx, v);
                }
            }
        } else {
            #pragma unroll
            for (int dy = -3; dy <= 3; ++dy) {
                int yy = iy + dy; float wy = 1.f;
                if (yy < 0) { yy = 0; wy = 0.5f; } else if (yy > 127) { yy = 127; wy = 0.5f; }
                #pragma unroll
                for (int dx = -3; dx <= 3; ++dx) {
                    int xx = ix + dx; float wx = wy;
                    if (xx < 0) { xx = 0; wx *= 0.5f; } else if (xx > 127) { xx = 127; wx *= 0.5f; }
                    float v = sp[(yy - r0) * K3PITCH + xx] * wx;
                    sum += v; mx = fmaxf(mx, v);
                }
            }
        }
        float r = 0.5f * (sum * (1.f / 49.f) + mx);
        if (src == 0) {
            g_vmt[(b * CH + c) * NPAD + p] = r;
        } else {
            g_vat[(b * CH + c) * NPAD + p] = r;
            g_vaux[(b * NPAD + p) * CH + c] = r;
        }
    }
}

// ================= kernel 4: tf32 mma attention, 32-row tiles, 3-deep cp.async =================
#define T_QT 0
#define T_S  10240
#define T_B  26880
#define T_VH 43776
#define T_TOT 52224
#define BSTR 4224

__global__ void __launch_bounds__(512, 1)
k4_attn(const float* __restrict__ fc1w, const float* __restrict__ fc1b,
        const float* __restrict__ fc2w, const float* __restrict__ fc2b,
        const float* __restrict__ pw,   const float* __restrict__ pb,
        float* __restrict__ out) {
    extern __shared__ float sm[];
    float* Qt = sm + T_QT;
    float* S  = sm + T_S;
    float* Bf = sm + T_B;
    float* Vh = sm + T_VH;

    const int t = threadIdx.x, lane = t & 31, w = t >> 5;
    const int gid = lane >> 2, tig = lane & 3;
    const int b = blockIdx.y;
    const int r0 = blockIdx.x * 32;
    const int nrows = min(32, NPTS - r0);

    for (int idx4 = t; idx4 < 2048; idx4 += 512) {
        int k = idx4 >> 3, i4 = (idx4 & 7) * 4;
        float4 v = *reinterpret_cast<const float4*>(&g_vmt[(b * CH + k) * NPAD + r0 + i4]);
        *reinterpret_cast<float4*>(&Qt[k * 40 + i4]) = v;
    }

    // ---- GEMM1 ----
    {
        float dq[2][4][4] = {};
        const int ntb = w * 4;
        #pragma unroll
        for (int p = 0; p < 3; ++p) {
            #pragma unroll
            for (int ii = 0; ii < 2; ++ii) {
                int op = t + ii * 512;
                int row = op >> 7, ch = op & 127;
                cp16(&Bf[p * BSTR + row * 520 + ch * 4],
                     &g_vat[(size_t)(b * CH + p * 8 + row) * NPAD + ch * 4]);
            }
            CP_COMMIT();
        }
        for (int s = 0; s < 32; ++s) {
            if (s + 3 < 32) {
                int kbase = 8 * (s + 3);
                int bufo = ((s + 3) & 3) * BSTR;
                #pragma unroll
                for (int ii = 0; ii < 2; ++ii) {
                    int op = t + ii * 512;
                    int row = op >> 7, ch = op & 127;
                    cp16(&Bf[bufo + row * 520 + ch * 4],
                         &g_vat[(size_t)(b * CH + kbase + row) * NPAD + ch * 4]);
                }
            }
            CP_COMMIT();
            CP_WAIT3();
            __syncthreads();
            const uint32_t* KS  = (const uint32_t*)&Bf[(s & 3) * BSTR];
            const uint32_t* QtU = (const uint32_t*)Qt;
            uint32_t A[2][4];
            int ka = (8 * s + tig) * 40;
            int kb = (8 * s + tig + 4) * 40;
            #pragma unroll
            for (int mt = 0; mt < 2; ++mt) {
                int r = mt * 16 + gid;
                A[mt][0] = QtU[ka + r];
                A[mt][1] = QtU[ka + r + 8];
                A[mt][2] = QtU[kb + r];
                A[mt][3] = QtU[kb + r + 8];
            }
            #pragma unroll
            for (int j = 0; j < 4; ++j) {
                int n0 = (ntb + j) * 8 + gid;
                uint32_t B[2];
                B[0] = KS[tig * 520 + n0];
                B[1] = KS[(tig + 4) * 520 + n0];
                mma8(dq[0][j], A[0], B);
                mma8(dq[1][j], A[1], B);
            }
            __syncthreads();
        }
        #pragma unroll
        for (int mt = 0; mt < 2; ++mt) {
            #pragma unroll
            for (int j = 0; j < 4; ++j) {
                int r = mt * 16 + gid;
                int n0 = (ntb + j) * 8 + 2 * tig;
                S[r * 520 + n0]           = dq[mt][j][0] * 0.0625f;
                S[r * 520 + n0 + 1]       = dq[mt][j][1] * 0.0625f;
                S[(r + 8) * 520 + n0]     = dq[mt][j][2] * 0.0625f;
                S[(r + 8) * 520 + n0 + 1] = dq[mt][j][3] * 0.0625f;
            }
        }
        __syncthreads();
    }

    // ---- softmax ----
    #pragma unroll
    for (int i = 0; i < 2; ++i) {
        int r = 2 * w + i;
        float mxv = -CUDART_INF_F;
        for (int m = lane; m < NPTS; m += 32) mxv = fmaxf(mxv, S[r * 520 + m]);
        #pragma unroll
        for (int o = 16; o; o >>= 1) mxv = fmaxf(mxv, __shfl_xor_sync(0xffffffffu, mxv, o));
        float sum = 0.f;
        for (int m = lane; m < NPTS; m += 32) {
            float e = __expf(S[r * 520 + m] - mxv);
            S[r * 520 + m] = e;
            sum += e;
        }
        #pragma unroll
        for (int o = 16; o; o >>= 1) sum += __shfl_xor_sync(0xffffffffu, sum, o);
        float inv = 1.f / sum;
        for (int m = lane; m < 512; m += 32) {
            float v = (m < NPTS) ? S[r * 520 + m] * inv : 0.f;
            S[r * 520 + m] = v;
        }
    }
    __syncthreads();

    // ---- GEMM2 ----
    {
        float dv[2][2][4] = {};
        const int ntb2 = w * 2;
        #pragma unroll
        for (int p = 0; p < 3; ++p) {
            #pragma unroll
            for (int ii = 0; ii < 2; ++ii) {
                int op = t + ii * 512;
                int row = op >> 6, ch = op & 63;
                cp16(&Bf[p * BSTR + row * 264 + ch * 4],
                     &g_vaux[(size_t)(b * NPAD + p * 16 + row) * CH + ch * 4]);
            }
            CP_COMMIT();
        }
        for (int s = 0; s < 32; ++s) {
            if (s + 3 < 32) {
                int mb = 16 * (s + 3);
                int bufo = ((s + 3) & 3) * BSTR;
                #pragma unroll
                for (int ii = 0; ii < 2; ++ii) {
                    int op = t + ii * 512;
                    int row = op >> 6, ch = op & 63;
                    cp16(&Bf[bufo + row * 264 + ch * 4],
                         &g_vaux[(size_t)(b * NPAD + mb + row) * CH + ch * 4]);
                }
            }
            CP_COMMIT();
            CP_WAIT3();
            __syncthreads();
            const uint32_t* VS = (const uint32_t*)&Bf[(s & 3) * BSTR];
            const uint32_t* PU = (const uint32_t*)S;
            #pragma unroll
            for (int kk = 0; kk < 2; ++kk) {
                int k0 = 16 * s + 8 * kk;
                uint32_t A[2][4];
                #pragma unroll
                for (int mt = 0; mt < 2; ++mt) {
                    int r = mt * 16 + gid;
                    A[mt][0] = PU[r * 520 + k0 + tig];
                    A[mt][1] = PU[(r + 8) * 520 + k0 + tig];
                    A[mt][2] = PU[r * 520 + k0 + tig + 4];
                    A[mt][3] = PU[(r + 8) * 520 + k0 + tig + 4];
                }
                #pragma unroll
                for (int j = 0; j < 2; ++j) {
                    int n0 = (ntb2 + j) * 8 + gid;
                    uint32_t B[2];
                    B[0] = VS[(8 * kk + tig) * 264 + n0];
                    B[1] = VS[(8 * kk + tig + 4) * 264 + n0];
                    mma8(dv[0][j], A[0], B);
                    mma8(dv[1][j], A[1], B);
                }
            }
            __syncthreads();
        }
        #pragma unroll
        for (int mt = 0; mt < 2; ++mt) {
            #pragma unroll
            for (int j = 0; j < 2; ++j) {
                int r = mt * 16 + gid;
                int n0 = (ntb2 + j) * 8 + 2 * tig;
                Vh[r * 264 + n0]           = dv[mt][j][0];
                Vh[r * 264 + n0 + 1]       = dv[mt][j][1];
                Vh[(r + 8) * 264 + n0]     = dv[mt][j][2];
                Vh[(r + 8) * 264 + n0 + 1] = dv[mt][j][3];
            }
        }
        __syncthreads();
    }

    // ---- gated fusion MLP ----
    CP_WAIT0();
    float* W1p = Bf;
    float* Vf  = S;
    float* W2s = Bf + 8192;
    for (int idx = t; idx < 4096; idx += 512) {
        int k = idx >> 4, j = idx & 15;
        float wa = fc1w[idx];
        float wb = fc1w[4096 + idx];
        float wc = fc1w[8192 + idx];
        W1p[k * 32 + 2 * j]     = wa + wc;
        W1p[k * 32 + 2 * j + 1] = wb - wc;
    }
    for (int idx = t; idx < 4096; idx += 512) W2s[idx] = fc2w[idx];
    __syncthreads();

    int jl = lane & 15, half = lane >> 4;
    float hreg[2];
    #pragma unroll
    for (int i = 0; i < 2; ++i) {
        int r = 2 * w + i;
        u64 hp = pk2(0.f, 0.f);
        int k0 = half * 128;
        #pragma unroll 4
        for (int k = k0; k < k0 + 128; ++k) {
            float vm = Qt[k * 40 + r];
            float vh = Vh[r * 264 + k];
            u64 wv = *reinterpret_cast<const u64*>(&W1p[k * 32 + 2 * jl]);
            hp = f2fma(pk2(vm, vh), wv, hp);
        }
        float hx, hy; upk2(hx, hy, hp);
        float h = hx + hy;
        h += __shfl_xor_sync(0xffffffffu, h, 16);
        h += fc1b[jl];
        hreg[i] = fmaxf(h, 0.f);
    }
    #pragma unroll
    for (int i = 0; i < 2; ++i) {
        int r = 2 * w + i;
        for (int cb = 0; cb < 256; cb += 32) {
            int c = cb + lane;
            float gg = fc2b[c];
            #pragma unroll
            for (int jj = 0; jj < 16; ++jj)
                gg += __shfl_sync(0xffffffffu, hreg[i], jj) * W2s[jj * 256 + c];
            gg = 1.f / (1.f + __expf(-gg));
            float vm = Qt[c * 40 + r];
            float vh = Vh[r * 264 + c];
            Vf[r * 264 + c] = vm + gg * (vm - vh);
        }
    }
    __syncthreads();

    // ---- GEMM3 + scatter ----
    {
        float dp[2][2][4] = {};
        const int ntb3 = w * 2;
        #pragma unroll
        for (int p = 0; p < 3; ++p) {
            #pragma unroll
            for (int ii = 0; ii < 2; ++ii) {
                int op = t + ii * 512;
                int row = op >> 6, ch = op & 63;
                cp16(&Bf[p * BSTR + row * 264 + ch * 4],
                     &pw[(size_t)(p * 16 + row) * 256 + ch * 4]);
            }
            CP_COMMIT();
        }
        for (int s = 0; s < 16; ++s) {
            if (s + 3 < 16) {
                int kbse = 16 * (s + 3);
                int bufo = ((s + 3) & 3) * BSTR;
                #pragma unroll
                for (int ii = 0; ii < 2; ++ii) {
                    int op = t + ii * 512;
                    int row = op >> 6, ch = op & 63;
                    cp16(&Bf[bufo + row * 264 + ch * 4],
                         &pw[(size_t)(kbse + row) * 256 + ch * 4]);
                }
            }
            CP_COMMIT();
            CP_WAIT3();
            __syncthreads();
            const uint32_t* WS = (const uint32_t*)&Bf[(s & 3) * BSTR];
            const uint32_t* FU = (const uint32_t*)Vf;
            #pragma unroll
            for (int kk = 0; kk < 2; ++kk) {
                int k0 = 16 * s + 8 * kk;
                uint32_t A[2][4];
                #pragma unroll
                for (int mt = 0; mt < 2; ++mt) {
                    int r = mt * 16 + gid;
                    A[mt][0] = FU[r * 264 + k0 + tig];
                    A[mt][1] = FU[(r + 8) * 264 + k0 + tig];
                    A[mt][2] = FU[r * 264 + k0 + tig + 4];
                    A[mt][3] = FU[(r + 8) * 264 + k0 + tig + 4];
                }
                #pragma unroll
                for (int j = 0; j < 2; ++j) {
                    int n0 = (ntb3 + j) * 8 + gid;
                    uint32_t B[2];
                    B[0] = WS[(8 * kk + tig) * 264 + n0];
                    B[1] = WS[(8 * kk + tig + 4) * 264 + n0];
                    mma8(dp[0][j], A[0], B);
                    mma8(dp[1][j], A[1], B);
                }
            }
            __syncthreads();
        }
        #pragma unroll
        for (int mt = 0; mt < 2; ++mt) {
            int r = mt * 16 + gid;
            int hw0 = (r < nrows)     ? g_idx[b * NPTS + r0 + r]     : -1;
            int hw1 = (r + 8 < nrows) ? g_idx[b * NPTS + r0 + r + 8] : -1;
            #pragma unroll
            for (int j = 0; j < 2; ++j) {
                int c = (ntb3 + j) * 8 + 2 * tig;
                float pb0 = pb[c], pb1 = pb[c + 1];
                if (hw0 >= 0) {
                    float* o0 = out + (size_t)(b * CH + c) * HWSZ + hw0;
                    o0[0]    += dp[mt][j][0] + pb0;
                    o0[HWSZ] += dp[mt][j][1] + pb1;
                }
                if (hw1 >= 0) {
                    float* o1 = out + (size_t)(b * CH + c) * HWSZ + hw1;
                    o1[0]    += dp[mt][j][2] + pb0;
                    o1[HWSZ] += dp[mt][j][3] + pb1;
                }
            }
        }
    }
}

// ================= launch =================
extern "C" void kernel_launch(void* const* d_in, const int* in_sizes, int n_in,
                              void* d_out, int out_size) {
    const float* xm   = (const float*)d_in[0];
    const float* xa   = (const float*)d_in[1];
    const float* sw   = (const float*)d_in[2];
    const float* fc1w = (const float*)d_in[4];
    const float* fc1b = (const float*)d_in[5];
    const float* fc2w = (const float*)d_in[6];
    const float* fc2b = (const float*)d_in[7];
    const float* pw   = (const float*)d_in[8];
    const float* pb   = (const float*)d_in[9];
    float* out = (float*)d_out;

    const int K3_SMEM = K3ROWS * K3PITCH * 4 + NPAD * 4;   // 37424 B
    const int K4_SMEM = T_TOT * 4;                         // 208896 B
    cudaFuncSetAttribute(k3_pool, cudaFuncAttributeMaxDynamicSharedMemorySize, K3_SMEM);
    cudaFuncSetAttribute(k4_attn, cudaFuncAttributeMaxDynamicSharedMemorySize, K4_SMEM);

    k1_copy_score<<<dim3(512, 2), 256>>>(xm, sw, out);
    k2_topk<<<BATCH, 512>>>();
    k3_pool<<<dim3(CH, BATCH, 4), 256, K3_SMEM>>>(xm, xa);
    k4_attn<<<dim3(16, BATCH), 512, K4_SMEM>>>(fc1w, fc1b, fc2w, fc2b, pw, pb, out);
}